// round 1
// baseline (speedup 1.0000x reference)
#include <cuda_runtime.h>
#include <math.h>

#define NB 2
#define NT 2048
#define NC 1024
#define NH 16
#define ND 64
#define NM (NB*NT)   // 4096 rows

// Scratch (allocation-free): Q,K,V in [B,H,T,D], Y in [B,T,C]
__device__ float g_Q[NB*NH*NT*ND];
__device__ float g_K[NB*NH*NT*ND];
__device__ float g_V[NB*NH*NT*ND];
__device__ float g_Y[NM*NC];

// ---------------------------------------------------------------------------
// NT SGEMM: C[m][n] = sum_k A[m][k] * W[n][k] + bias[n]
// M=4096, N=1024, K=1024. BM=BN=128, BK=16, 256 threads, 8x8 per thread.
// OUT_MODE 0: row-major [M][N]; OUT_MODE 1: scatter to [B,H,T,D].
// ---------------------------------------------------------------------------
template<int OUT_MODE>
__global__ __launch_bounds__(256, 1)
void gemm_nt(const float* __restrict__ A, const float* __restrict__ W,
             const float* __restrict__ bias, float* __restrict__ Cout)
{
    const int K = NC;
    __shared__ __align__(16) float As[16][132];
    __shared__ __align__(16) float Bs[16][132];

    int tid = threadIdx.x;
    int tx = tid & 15, ty = tid >> 4;
    int m0 = blockIdx.y * 128;
    int n0 = blockIdx.x * 128;

    float acc[8][8];
    #pragma unroll
    for (int i = 0; i < 8; i++)
        #pragma unroll
        for (int j = 0; j < 8; j++) acc[i][j] = 0.f;

    for (int k0 = 0; k0 < K; k0 += 16) {
        // Load 128x16 tiles of A and W, stored transposed [k][m]/[k][n]
        #pragma unroll
        for (int it = 0; it < 2; it++) {
            int idx = tid + it * 256;          // 0..511
            int row = idx >> 2;                // 0..127
            int kc  = (idx & 3) << 2;          // 0,4,8,12
            float4 va = *(const float4*)&A[(size_t)(m0 + row) * K + k0 + kc];
            As[kc + 0][row] = va.x; As[kc + 1][row] = va.y;
            As[kc + 2][row] = va.z; As[kc + 3][row] = va.w;
            float4 vb = *(const float4*)&W[(size_t)(n0 + row) * K + k0 + kc];
            Bs[kc + 0][row] = vb.x; Bs[kc + 1][row] = vb.y;
            Bs[kc + 2][row] = vb.z; Bs[kc + 3][row] = vb.w;
        }
        __syncthreads();

        #pragma unroll
        for (int kk = 0; kk < 16; kk++) {
            float a[8], b[8];
            *(float4*)&a[0] = *(const float4*)&As[kk][ty * 8];
            *(float4*)&a[4] = *(const float4*)&As[kk][ty * 8 + 4];
            *(float4*)&b[0] = *(const float4*)&Bs[kk][tx * 8];
            *(float4*)&b[4] = *(const float4*)&Bs[kk][tx * 8 + 4];
            #pragma unroll
            for (int i = 0; i < 8; i++)
                #pragma unroll
                for (int j = 0; j < 8; j++)
                    acc[i][j] = fmaf(a[i], b[j], acc[i][j]);
        }
        __syncthreads();
    }

    #pragma unroll
    for (int i = 0; i < 8; i++) {
        int m = m0 + ty * 8 + i;
        #pragma unroll
        for (int j = 0; j < 8; j++) {
            int n = n0 + tx * 8 + j;
            float val = acc[i][j] + bias[n];
            if (OUT_MODE == 0) {
                Cout[(size_t)m * NC + n] = val;
            } else {
                int b = m >> 11, t = m & (NT - 1);
                int h = n >> 6,  d = n & 63;
                Cout[(((size_t)(b * NH + h) * NT) + t) * ND + d] = val;
            }
        }
    }
}

// ---------------------------------------------------------------------------
// Causal flash attention. Q/K/V in [B,H,T,D], output Y in [B,T,C].
// Block: 64 q-rows of one (b,h). 256 threads, 4x4 micro-tiles.
// smem (dynamic, 66560B): Qs/Ks/Vs/Ps each [64][65]
// ---------------------------------------------------------------------------
__global__ __launch_bounds__(256, 1)
void attn_kernel(const float* __restrict__ Q, const float* __restrict__ K,
                 const float* __restrict__ V, float* __restrict__ Y)
{
    extern __shared__ __align__(16) float smem[];
    float (*Qs)[65] = (float(*)[65])(smem);
    float (*Ks)[65] = (float(*)[65])(smem + 64 * 65);
    float (*Vs)[65] = (float(*)[65])(smem + 2 * 64 * 65);
    float (*Ps)[65] = (float(*)[65])(smem + 3 * 64 * 65);

    int tid = threadIdx.x;
    int tx = tid & 15, ty = tid >> 4;
    int qb = blockIdx.x;      // q block (64 rows)
    int bh = blockIdx.y;      // b*NH + h

    const float* Qg = Q + ((size_t)bh * NT + qb * 64) * ND;
    const float* Kg = K + (size_t)bh * NT * ND;
    const float* Vg = V + (size_t)bh * NT * ND;

    // Load Q tile
    for (int i = tid; i < 64 * 16; i += 256) {
        int r = i >> 4, c = (i & 15) << 2;
        float4 v = *(const float4*)&Qg[r * ND + c];
        Qs[r][c] = v.x; Qs[r][c + 1] = v.y; Qs[r][c + 2] = v.z; Qs[r][c + 3] = v.w;
    }

    float m_i[4], l_i[4], o[4][4];
    #pragma unroll
    for (int i = 0; i < 4; i++) {
        m_i[i] = -1e30f; l_i[i] = 0.f;
        #pragma unroll
        for (int j = 0; j < 4; j++) o[i][j] = 0.f;
    }
    const float scale = 0.125f;   // 1/sqrt(64)

    for (int kb = 0; kb <= qb; kb++) {
        __syncthreads();   // prior iteration done reading Ks/Vs/Ps (also covers Qs fill)
        for (int i = tid; i < 64 * 16; i += 256) {
            int r = i >> 4, c = (i & 15) << 2;
            float4 v = *(const float4*)&Kg[(size_t)(kb * 64 + r) * ND + c];
            Ks[r][c] = v.x; Ks[r][c + 1] = v.y; Ks[r][c + 2] = v.z; Ks[r][c + 3] = v.w;
            float4 w = *(const float4*)&Vg[(size_t)(kb * 64 + r) * ND + c];
            Vs[r][c] = w.x; Vs[r][c + 1] = w.y; Vs[r][c + 2] = w.z; Vs[r][c + 3] = w.w;
        }
        __syncthreads();

        // S = Q K^T (4x4 per thread)
        float s[4][4];
        #pragma unroll
        for (int i = 0; i < 4; i++)
            #pragma unroll
            for (int j = 0; j < 4; j++) s[i][j] = 0.f;

        #pragma unroll 4
        for (int d = 0; d < ND; d++) {
            float a[4], b[4];
            #pragma unroll
            for (int i = 0; i < 4; i++) {
                a[i] = Qs[ty * 4 + i][d];
                b[i] = Ks[tx * 4 + i][d];
            }
            #pragma unroll
            for (int i = 0; i < 4; i++)
                #pragma unroll
                for (int j = 0; j < 4; j++)
                    s[i][j] = fmaf(a[i], b[j], s[i][j]);
        }

        bool diag = (kb == qb);
        // Online softmax per row (16 lanes share a row; lane = (ty&1)*16+tx)
        #pragma unroll
        for (int i = 0; i < 4; i++) {
            int r = ty * 4 + i;
            float sv[4];
            #pragma unroll
            for (int j = 0; j < 4; j++) {
                float v = s[i][j] * scale;
                if (diag && (tx * 4 + j) > r) v = -1e30f;
                sv[j] = v;
            }
            float mx = fmaxf(fmaxf(sv[0], sv[1]), fmaxf(sv[2], sv[3]));
            #pragma unroll
            for (int off = 1; off < 16; off <<= 1)
                mx = fmaxf(mx, __shfl_xor_sync(0xffffffffu, mx, off));
            float mnew = fmaxf(m_i[i], mx);
            float ps = 0.f;
            #pragma unroll
            for (int j = 0; j < 4; j++) {
                float p = __expf(sv[j] - mnew);
                Ps[r][tx * 4 + j] = p;
                ps += p;
            }
            #pragma unroll
            for (int off = 1; off < 16; off <<= 1)
                ps += __shfl_xor_sync(0xffffffffu, ps, off);
            float f = __expf(m_i[i] - mnew);
            l_i[i] = l_i[i] * f + ps;
            m_i[i] = mnew;
            #pragma unroll
            for (int j = 0; j < 4; j++) o[i][j] *= f;
        }
        __syncthreads();

        // O += P V
        #pragma unroll 4
        for (int k = 0; k < 64; k++) {
            float p[4], v[4];
            #pragma unroll
            for (int i = 0; i < 4; i++) {
                p[i] = Ps[ty * 4 + i][k];
                v[i] = Vs[k][tx * 4 + i];
            }
            #pragma unroll
            for (int i = 0; i < 4; i++)
                #pragma unroll
                for (int j = 0; j < 4; j++)
                    o[i][j] = fmaf(p[i], v[j], o[i][j]);
        }
    }

    // Write Y[b, t, h*64 + c]
    int b = bh >> 4, h = bh & 15;
    float* Yg = Y + ((size_t)b * NT + qb * 64) * NC + h * ND;
    #pragma unroll
    for (int i = 0; i < 4; i++) {
        float inv = 1.f / l_i[i];
        #pragma unroll
        for (int j = 0; j < 4; j++)
            Yg[(size_t)(ty * 4 + i) * NC + tx * 4 + j] = o[i][j] * inv;
    }
}

static const int ATTN_SMEM = 4 * 64 * 65 * (int)sizeof(float);  // 66560

extern "C" void kernel_launch(void* const* d_in, const int* in_sizes, int n_in,
                              void* d_out, int out_size)
{
    const float* x  = (const float*)d_in[0];
    // d_in[1] = attn_mask (causal, implicit — unused)
    const float* Wq = (const float*)d_in[2];
    const float* bq = (const float*)d_in[3];
    const float* Wk = (const float*)d_in[4];
    const float* bk = (const float*)d_in[5];
    const float* Wv = (const float*)d_in[6];
    const float* bv = (const float*)d_in[7];
    const float* Wo = (const float*)d_in[8];
    const float* bo = (const float*)d_in[9];

    float *qp, *kp, *vp, *yp;
    cudaGetSymbolAddress((void**)&qp, g_Q);
    cudaGetSymbolAddress((void**)&kp, g_K);
    cudaGetSymbolAddress((void**)&vp, g_V);
    cudaGetSymbolAddress((void**)&yp, g_Y);

    cudaFuncSetAttribute(attn_kernel,
                         cudaFuncAttributeMaxDynamicSharedMemorySize, ATTN_SMEM);

    dim3 gridG(NC / 128, NM / 128);   // (8, 32)
    gemm_nt<1><<<gridG, 256>>>(x, Wq, bq, qp);
    gemm_nt<1><<<gridG, 256>>>(x, Wk, bk, kp);
    gemm_nt<1><<<gridG, 256>>>(x, Wv, bv, vp);
    attn_kernel<<<dim3(NT / 64, NB * NH), 256, ATTN_SMEM>>>(qp, kp, vp, yp);
    gemm_nt<0><<<gridG, 256>>>(yp, Wo, bo, (float*)d_out);
}

// round 6
// speedup vs baseline: 1.1159x; 1.1159x over previous
#include <cuda_runtime.h>
#include <math.h>
#include <stdint.h>

#define NB 2
#define NT 2048
#define NC 1024
#define NH 16
#define ND 64
#define NM (NB*NT)   // 4096 rows

// Scratch (allocation-free)
__device__ float g_Q[NB*NH*NT*ND];
__device__ float g_K[NB*NH*NT*ND];
__device__ float g_V[NB*NH*NT*ND];
__device__ float g_Y[NM*NC];
__device__ float g_xr[NM*NC];       // tf32-rounded x
__device__ float g_Wr[4*NC*NC];     // tf32-rounded Wq,Wk,Wv,Wo

// ---------------------------------------------------------------------------
// PTX helpers (arch-agnostic: sm_80-era instructions only)
// ---------------------------------------------------------------------------
__device__ __forceinline__ uint32_t smem_u32(const void* p) {
    uint32_t a;
    asm("{ .reg .u64 t; cvta.to.shared.u64 t, %1; cvt.u32.u64 %0, t; }" : "=r"(a) : "l"(p));
    return a;
}
__device__ __forceinline__ void cp_async16(uint32_t dst, const void* src) {
    asm volatile("cp.async.cg.shared.global [%0], [%1], 16;\n" :: "r"(dst), "l"(src));
}
__device__ __forceinline__ void cp_commit() { asm volatile("cp.async.commit_group;\n" ::: "memory"); }
__device__ __forceinline__ void cp_wait2() { asm volatile("cp.async.wait_group 2;\n" ::: "memory"); }

__device__ __forceinline__ void ldsm4(uint32_t* r, uint32_t addr) {
    asm volatile("ldmatrix.sync.aligned.m8n8.x4.shared.b16 {%0,%1,%2,%3}, [%4];"
        : "=r"(r[0]), "=r"(r[1]), "=r"(r[2]), "=r"(r[3]) : "r"(addr));
}
__device__ __forceinline__ void mma_tf32(float* d, const uint32_t* a, const uint32_t* b) {
    asm volatile(
        "mma.sync.aligned.m16n8k8.row.col.f32.tf32.tf32.f32 "
        "{%0,%1,%2,%3}, {%4,%5,%6,%7}, {%8,%9}, {%0,%1,%2,%3};"
        : "+f"(d[0]), "+f"(d[1]), "+f"(d[2]), "+f"(d[3])
        : "r"(a[0]), "r"(a[1]), "r"(a[2]), "r"(a[3]), "r"(b[0]), "r"(b[1]));
}
__device__ __forceinline__ uint32_t swz(uint32_t x) { return x ^ ((x >> 3) & 0x70); }

// ---------------------------------------------------------------------------
// RNA round-to-tf32 elementwise pass (in == out allowed)
// ---------------------------------------------------------------------------
__global__ void round_tf32_kernel(const float* __restrict__ in, float* __restrict__ out, int n4) {
    int i = blockIdx.x * blockDim.x + threadIdx.x;
    int stride = gridDim.x * blockDim.x;
    for (; i < n4; i += stride) {
        float4 v = ((const float4*)in)[i];
        uint32_t a, b, c, d;
        asm("cvt.rna.tf32.f32 %0, %1;" : "=r"(a) : "r"(__float_as_uint(v.x)));
        asm("cvt.rna.tf32.f32 %0, %1;" : "=r"(b) : "r"(__float_as_uint(v.y)));
        asm("cvt.rna.tf32.f32 %0, %1;" : "=r"(c) : "r"(__float_as_uint(v.z)));
        asm("cvt.rna.tf32.f32 %0, %1;" : "=r"(d) : "r"(__float_as_uint(v.w)));
        float4 o;
        o.x = __uint_as_float(a); o.y = __uint_as_float(b);
        o.z = __uint_as_float(c); o.w = __uint_as_float(d);
        ((float4*)out)[i] = o;
    }
}

// ---------------------------------------------------------------------------
// tf32 mma.sync GEMM: C[m][n] = sum_k A[m][k]*W[n][k] + bias[n]
// M=4096 N=1024 K=1024. BM=128 BN=128 BK=32 floats, 4-stage cp.async.
// 256 threads = 8 warps in 4(m) x 2(n); warp tile 32x64; m16n8k8 tf32.
// OUT_MODE 0: [M][N]; OUT_MODE 1: scatter [B,H,T,D].
// ---------------------------------------------------------------------------
#define BKF 32
#define NCHUNK (NC / BKF)                  // 32
#define STAGE_A 16384                      // 128 rows * 128 B
#define STAGE_BYTES (2 * STAGE_A)          // 32 KB
#define GEMM_SMEM (4 * STAGE_BYTES)        // 128 KB

template<int OUT_MODE>
__global__ __launch_bounds__(256, 1)
void gemm_tf32(const float* __restrict__ A, const float* __restrict__ W,
               const float* __restrict__ bias, float* __restrict__ Cout)
{
    extern __shared__ __align__(1024) char smem[];
    const uint32_t sbase = smem_u32(smem);
    const int tid = threadIdx.x;
    const int wid = tid >> 5, lane = tid & 31;
    const int m0 = blockIdx.y * 128;
    const int n0 = blockIdx.x * 128;

    const int warp_m = (wid >> 1) * 32;
    const int warp_n = (wid & 1) * 64;

    // ldmatrix lane-dependent offsets
    const uint32_t arow = warp_m + (lane & 15);
    const uint32_t achunk = (lane & 16) ? 16u : 0u;
    const uint32_t brow = warp_n + (lane & 7) + ((lane & 16) ? 8u : 0u);
    const uint32_t bchunk = (lane & 8) ? 16u : 0u;

    float acc[2][8][4];
    #pragma unroll
    for (int mi = 0; mi < 2; mi++)
        #pragma unroll
        for (int j = 0; j < 8; j++)
            #pragma unroll
            for (int q = 0; q < 4; q++) acc[mi][j][q] = 0.f;

    auto load_stage = [&](int s, int chunk) {
        const int kc = chunk * BKF;
        const uint32_t stA = sbase + s * STAGE_BYTES;
        const uint32_t stB = stA + STAGE_A;
        #pragma unroll
        for (int t = 0; t < 8; t++) {
            int i = tid + t * 256;          // 0..2047
            uint32_t off; const float* src;
            if (i < 1024) {
                int r = i >> 3, c16 = i & 7;
                off = stA + (uint32_t)(r * 128 + c16 * 16);
                src = A + (size_t)(m0 + r) * NC + kc + c16 * 4;
            } else {
                int j = i - 1024;
                int r = j >> 3, c16 = j & 7;
                off = stB + (uint32_t)(r * 128 + c16 * 16);
                src = W + (size_t)(n0 + r) * NC + kc + c16 * 4;
            }
            cp_async16(swz(off), src);
        }
    };

    load_stage(0, 0); cp_commit();
    load_stage(1, 1); cp_commit();
    load_stage(2, 2); cp_commit();

    for (int c = 0; c < NCHUNK; c++) {
        const int s = c & 3;
        cp_wait2();
        __syncthreads();

        if (c + 3 < NCHUNK) load_stage((c + 3) & 3, c + 3);
        cp_commit();

        const uint32_t SA = sbase + s * STAGE_BYTES;
        const uint32_t SB = SA + STAGE_A;
        #pragma unroll
        for (int ks = 0; ks < 4; ks++) {
            uint32_t af[2][4];
            ldsm4(af[0], SA + swz(arow * 128 + ks * 32 + achunk));
            ldsm4(af[1], SA + swz((arow + 16) * 128 + ks * 32 + achunk));
            uint32_t bf[4][4];
            #pragma unroll
            for (int p = 0; p < 4; p++)
                ldsm4(bf[p], SB + swz((brow + p * 16) * 128 + ks * 32 + bchunk));
            #pragma unroll
            for (int mi = 0; mi < 2; mi++)
                #pragma unroll
                for (int j = 0; j < 8; j++)
                    mma_tf32(acc[mi][j], af[mi], &bf[j >> 1][(j & 1) * 2]);
        }
    }

    // Epilogue: direct float2 stores with bias
    #pragma unroll
    for (int mi = 0; mi < 2; mi++) {
        int r0 = m0 + warp_m + mi * 16 + (lane >> 2);
        #pragma unroll
        for (int j = 0; j < 8; j++) {
            int col = n0 + warp_n + j * 8 + (lane & 3) * 2;
            float bx = __ldg(bias + col), by = __ldg(bias + col + 1);
            float2 v0 = make_float2(acc[mi][j][0] + bx, acc[mi][j][1] + by);
            float2 v1 = make_float2(acc[mi][j][2] + bx, acc[mi][j][3] + by);
            if (OUT_MODE == 0) {
                *(float2*)&Cout[(size_t)r0 * NC + col] = v0;
                *(float2*)&Cout[(size_t)(r0 + 8) * NC + col] = v1;
            } else {
                int h = col >> 6, d = col & 63;
                int b0i = r0 >> 11, t0 = r0 & (NT - 1);
                int b1i = (r0 + 8) >> 11, t1 = (r0 + 8) & (NT - 1);
                *(float2*)&Cout[(((size_t)(b0i * NH + h) * NT) + t0) * ND + d] = v0;
                *(float2*)&Cout[(((size_t)(b1i * NH + h) * NT) + t1) * ND + d] = v1;
            }
        }
    }
}

// ---------------------------------------------------------------------------
// Causal flash attention (unchanged). Q/K/V [B,H,T,D] -> Y [B,T,C].
// ---------------------------------------------------------------------------
__global__ __launch_bounds__(256, 1)
void attn_kernel(const float* __restrict__ Q, const float* __restrict__ K,
                 const float* __restrict__ V, float* __restrict__ Y)
{
    extern __shared__ __align__(16) float smemf[];
    float (*Qs)[65] = (float(*)[65])(smemf);
    float (*Ks)[65] = (float(*)[65])(smemf + 64 * 65);
    float (*Vs)[65] = (float(*)[65])(smemf + 2 * 64 * 65);
    float (*Ps)[65] = (float(*)[65])(smemf + 3 * 64 * 65);

    int tid = threadIdx.x;
    int tx = tid & 15, ty = tid >> 4;
    int qb = blockIdx.x;
    int bh = blockIdx.y;

    const float* Qg = Q + ((size_t)bh * NT + qb * 64) * ND;
    const float* Kg = K + (size_t)bh * NT * ND;
    const float* Vg = V + (size_t)bh * NT * ND;

    for (int i = tid; i < 64 * 16; i += 256) {
        int r = i >> 4, c = (i & 15) << 2;
        float4 v = *(const float4*)&Qg[r * ND + c];
        Qs[r][c] = v.x; Qs[r][c + 1] = v.y; Qs[r][c + 2] = v.z; Qs[r][c + 3] = v.w;
    }

    float m_i[4], l_i[4], o[4][4];
    #pragma unroll
    for (int i = 0; i < 4; i++) {
        m_i[i] = -1e30f; l_i[i] = 0.f;
        #pragma unroll
        for (int j = 0; j < 4; j++) o[i][j] = 0.f;
    }
    const float scale = 0.125f;

    for (int kb = 0; kb <= qb; kb++) {
        __syncthreads();
        for (int i = tid; i < 64 * 16; i += 256) {
            int r = i >> 4, c = (i & 15) << 2;
            float4 v = *(const float4*)&Kg[(size_t)(kb * 64 + r) * ND + c];
            Ks[r][c] = v.x; Ks[r][c + 1] = v.y; Ks[r][c + 2] = v.z; Ks[r][c + 3] = v.w;
            float4 w = *(const float4*)&Vg[(size_t)(kb * 64 + r) * ND + c];
            Vs[r][c] = w.x; Vs[r][c + 1] = w.y; Vs[r][c + 2] = w.z; Vs[r][c + 3] = w.w;
        }
        __syncthreads();

        float s[4][4];
        #pragma unroll
        for (int i = 0; i < 4; i++)
            #pragma unroll
            for (int j = 0; j < 4; j++) s[i][j] = 0.f;

        #pragma unroll 4
        for (int d = 0; d < ND; d++) {
            float a[4], b[4];
            #pragma unroll
            for (int i = 0; i < 4; i++) {
                a[i] = Qs[ty * 4 + i][d];
                b[i] = Ks[tx * 4 + i][d];
            }
            #pragma unroll
            for (int i = 0; i < 4; i++)
                #pragma unroll
                for (int j = 0; j < 4; j++)
                    s[i][j] = fmaf(a[i], b[j], s[i][j]);
        }

        bool diag = (kb == qb);
        #pragma unroll
        for (int i = 0; i < 4; i++) {
            int r = ty * 4 + i;
            float sv[4];
            #pragma unroll
            for (int j = 0; j < 4; j++) {
                float v = s[i][j] * scale;
                if (diag && (tx * 4 + j) > r) v = -1e30f;
                sv[j] = v;
            }
            float mx = fmaxf(fmaxf(sv[0], sv[1]), fmaxf(sv[2], sv[3]));
            #pragma unroll
            for (int off = 1; off < 16; off <<= 1)
                mx = fmaxf(mx, __shfl_xor_sync(0xffffffffu, mx, off));
            float mnew = fmaxf(m_i[i], mx);
            float ps = 0.f;
            #pragma unroll
            for (int j = 0; j < 4; j++) {
                float p = __expf(sv[j] - mnew);
                Ps[r][tx * 4 + j] = p;
                ps += p;
            }
            #pragma unroll
            for (int off = 1; off < 16; off <<= 1)
                ps += __shfl_xor_sync(0xffffffffu, ps, off);
            float f = __expf(m_i[i] - mnew);
            l_i[i] = l_i[i] * f + ps;
            m_i[i] = mnew;
            #pragma unroll
            for (int j = 0; j < 4; j++) o[i][j] *= f;
        }
        __syncthreads();

        #pragma unroll 4
        for (int k = 0; k < 64; k++) {
            float p[4], v[4];
            #pragma unroll
            for (int i = 0; i < 4; i++) {
                p[i] = Ps[ty * 4 + i][k];
                v[i] = Vs[k][tx * 4 + i];
            }
            #pragma unroll
            for (int i = 0; i < 4; i++)
                #pragma unroll
                for (int j = 0; j < 4; j++)
                    o[i][j] = fmaf(p[i], v[j], o[i][j]);
        }
    }

    int b = bh >> 4, h = bh & 15;
    float* Yg = Y + ((size_t)b * NT + qb * 64) * NC + h * ND;
    #pragma unroll
    for (int i = 0; i < 4; i++) {
        float inv = 1.f / l_i[i];
        #pragma unroll
        for (int j = 0; j < 4; j++)
            Yg[(size_t)(ty * 4 + i) * NC + tx * 4 + j] = o[i][j] * inv;
    }
}

static const int ATTN_SMEM = 4 * 64 * 65 * (int)sizeof(float);  // 66560

extern "C" void kernel_launch(void* const* d_in, const int* in_sizes, int n_in,
                              void* d_out, int out_size)
{
    const float* x  = (const float*)d_in[0];
    const float* Wq = (const float*)d_in[2];
    const float* bq = (const float*)d_in[3];
    const float* Wk = (const float*)d_in[4];
    const float* bk = (const float*)d_in[5];
    const float* Wv = (const float*)d_in[6];
    const float* bv = (const float*)d_in[7];
    const float* Wo = (const float*)d_in[8];
    const float* bo = (const float*)d_in[9];

    float *qp, *kp, *vp, *yp, *xr, *wr;
    cudaGetSymbolAddress((void**)&qp, g_Q);
    cudaGetSymbolAddress((void**)&kp, g_K);
    cudaGetSymbolAddress((void**)&vp, g_V);
    cudaGetSymbolAddress((void**)&yp, g_Y);
    cudaGetSymbolAddress((void**)&xr, g_xr);
    cudaGetSymbolAddress((void**)&wr, g_Wr);

    cudaFuncSetAttribute(attn_kernel,
                         cudaFuncAttributeMaxDynamicSharedMemorySize, ATTN_SMEM);
    cudaFuncSetAttribute(gemm_tf32<0>,
                         cudaFuncAttributeMaxDynamicSharedMemorySize, GEMM_SMEM);
    cudaFuncSetAttribute(gemm_tf32<1>,
                         cudaFuncAttributeMaxDynamicSharedMemorySize, GEMM_SMEM);

    // tf32 RNA rounding pre-passes
    round_tf32_kernel<<<512, 256>>>(x,  xr,            NM * NC / 4);
    round_tf32_kernel<<<256, 256>>>(Wq, wr + 0*NC*NC,  NC * NC / 4);
    round_tf32_kernel<<<256, 256>>>(Wk, wr + 1*NC*NC,  NC * NC / 4);
    round_tf32_kernel<<<256, 256>>>(Wv, wr + 2*NC*NC,  NC * NC / 4);
    round_tf32_kernel<<<256, 256>>>(Wo, wr + 3*NC*NC,  NC * NC / 4);

    dim3 gridG(NC / 128, NM / 128);   // (8, 32) = 256 CTAs
    gemm_tf32<1><<<gridG, 256, GEMM_SMEM>>>(xr, wr + 0*NC*NC, bq, qp);
    gemm_tf32<1><<<gridG, 256, GEMM_SMEM>>>(xr, wr + 1*NC*NC, bk, kp);
    gemm_tf32<1><<<gridG, 256, GEMM_SMEM>>>(xr, wr + 2*NC*NC, bv, vp);

    attn_kernel<<<dim3(NT / 64, NB * NH), 256, ATTN_SMEM>>>(qp, kp, vp, yp);

    round_tf32_kernel<<<512, 256>>>(yp, yp, NM * NC / 4);   // in-place round Y
    gemm_tf32<0><<<gridG, 256, GEMM_SMEM>>>(yp, wr + 3*NC*NC, bo, (float*)d_out);
}

// round 7
// speedup vs baseline: 2.5151x; 2.2539x over previous
#include <cuda_runtime.h>
#include <math.h>
#include <stdint.h>

#define NB 2
#define NT 2048
#define NC 1024
#define NH 16
#define ND 64
#define NM (NB*NT)   // 4096 rows

// Scratch (allocation-free)
__device__ float g_Q[NB*NH*NT*ND];
__device__ float g_K[NB*NH*NT*ND];
__device__ float g_V[NB*NH*NT*ND];
__device__ float g_Y[NM*NC];
__device__ float g_xr[NM*NC];       // tf32-rounded x
__device__ float g_Wr[4*NC*NC];     // tf32-rounded Wq,Wk,Wv,Wo

// ---------------------------------------------------------------------------
// PTX helpers (arch-agnostic: sm_80-era instructions only)
// ---------------------------------------------------------------------------
__device__ __forceinline__ uint32_t smem_u32(const void* p) {
    uint32_t a;
    asm("{ .reg .u64 t; cvta.to.shared.u64 t, %1; cvt.u32.u64 %0, t; }" : "=r"(a) : "l"(p));
    return a;
}
__device__ __forceinline__ void cp_async16(uint32_t dst, const void* src) {
    asm volatile("cp.async.cg.shared.global [%0], [%1], 16;\n" :: "r"(dst), "l"(src));
}
__device__ __forceinline__ void cp_commit() { asm volatile("cp.async.commit_group;\n" ::: "memory"); }
__device__ __forceinline__ void cp_wait1() { asm volatile("cp.async.wait_group 1;\n" ::: "memory"); }
__device__ __forceinline__ void cp_wait0() { asm volatile("cp.async.wait_group 0;\n" ::: "memory"); }

__device__ __forceinline__ void ldsm4(uint32_t* r, uint32_t addr) {
    asm volatile("ldmatrix.sync.aligned.m8n8.x4.shared.b16 {%0,%1,%2,%3}, [%4];"
        : "=r"(r[0]), "=r"(r[1]), "=r"(r[2]), "=r"(r[3]) : "r"(addr));
}
__device__ __forceinline__ void mma_tf32(float* d, const uint32_t* a, const uint32_t* b) {
    asm volatile(
        "mma.sync.aligned.m16n8k8.row.col.f32.tf32.tf32.f32 "
        "{%0,%1,%2,%3}, {%4,%5,%6,%7}, {%8,%9}, {%0,%1,%2,%3};"
        : "+f"(d[0]), "+f"(d[1]), "+f"(d[2]), "+f"(d[3])
        : "r"(a[0]), "r"(a[1]), "r"(a[2]), "r"(a[3]), "r"(b[0]), "r"(b[1]));
}
__device__ __forceinline__ uint32_t swz(uint32_t x) { return x ^ ((x >> 3) & 0x70); }
__device__ __forceinline__ float rna_tf32(float x) {
    uint32_t r;
    asm("cvt.rna.tf32.f32 %0, %1;" : "=r"(r) : "r"(__float_as_uint(x)));
    return __uint_as_float(r);
}

// ---------------------------------------------------------------------------
// RNA round-to-tf32 elementwise pass (in == out allowed)
// ---------------------------------------------------------------------------
__global__ void round_tf32_kernel(const float* __restrict__ in, float* __restrict__ out, int n4) {
    int i = blockIdx.x * blockDim.x + threadIdx.x;
    int stride = gridDim.x * blockDim.x;
    for (; i < n4; i += stride) {
        float4 v = ((const float4*)in)[i];
        float4 o;
        o.x = rna_tf32(v.x); o.y = rna_tf32(v.y);
        o.z = rna_tf32(v.z); o.w = rna_tf32(v.w);
        ((float4*)out)[i] = o;
    }
}

// ---------------------------------------------------------------------------
// tf32 mma.sync GEMM: C[m][n] = sum_k A[m][k]*W[n][k] + bias[n]
// BM=128 BN=128 BK=32 floats, 3-stage cp.async (96KB smem -> 2 CTAs/SM).
// 256 threads = 8 warps in 4(m) x 2(n); warp tile 32x64; m16n8k8 tf32.
// OUT_MODE 0: [M][N]; OUT_MODE 1: scatter [B,H,T,D] with RNA tf32 rounding.
// ---------------------------------------------------------------------------
#define BKF 32
#define NCHUNK (NC / BKF)                  // 32
#define STAGE_A 16384                      // 128 rows * 128 B
#define STAGE_BYTES (2 * STAGE_A)          // 32 KB
#define GEMM_SMEM (3 * STAGE_BYTES)        // 96 KB

template<int OUT_MODE>
__global__ __launch_bounds__(256, 2)
void gemm_tf32(const float* __restrict__ A, const float* __restrict__ W,
               const float* __restrict__ bias, float* __restrict__ Cout)
{
    extern __shared__ __align__(1024) char smem[];
    const uint32_t sbase = smem_u32(smem);
    const int tid = threadIdx.x;
    const int wid = tid >> 5, lane = tid & 31;
    const int m0 = blockIdx.y * 128;
    const int n0 = blockIdx.x * 128;

    const int warp_m = (wid >> 1) * 32;
    const int warp_n = (wid & 1) * 64;

    const uint32_t arow = warp_m + (lane & 15);
    const uint32_t achunk = (lane & 16) ? 16u : 0u;
    const uint32_t brow = warp_n + (lane & 7) + ((lane & 16) ? 8u : 0u);
    const uint32_t bchunk = (lane & 8) ? 16u : 0u;

    float acc[2][8][4];
    #pragma unroll
    for (int mi = 0; mi < 2; mi++)
        #pragma unroll
        for (int j = 0; j < 8; j++)
            #pragma unroll
            for (int q = 0; q < 4; q++) acc[mi][j][q] = 0.f;

    auto load_stage = [&](int s, int chunk) {
        const int kc = chunk * BKF;
        const uint32_t stA = sbase + s * STAGE_BYTES;
        const uint32_t stB = stA + STAGE_A;
        #pragma unroll
        for (int t = 0; t < 8; t++) {
            int i = tid + t * 256;
            uint32_t off; const float* src;
            if (i < 1024) {
                int r = i >> 3, c16 = i & 7;
                off = stA + (uint32_t)(r * 128 + c16 * 16);
                src = A + (size_t)(m0 + r) * NC + kc + c16 * 4;
            } else {
                int j = i - 1024;
                int r = j >> 3, c16 = j & 7;
                off = stB + (uint32_t)(r * 128 + c16 * 16);
                src = W + (size_t)(n0 + r) * NC + kc + c16 * 4;
            }
            cp_async16(swz(off), src);
        }
    };

    load_stage(0, 0); cp_commit();
    load_stage(1, 1); cp_commit();

    int s = 0;
    for (int c = 0; c < NCHUNK; c++) {
        cp_wait1();
        __syncthreads();

        if (c + 2 < NCHUNK) {
            int sp = s + 2; if (sp >= 3) sp -= 3;
            load_stage(sp, c + 2);
        }
        cp_commit();

        const uint32_t SA = sbase + s * STAGE_BYTES;
        const uint32_t SB = SA + STAGE_A;
        #pragma unroll
        for (int ks = 0; ks < 4; ks++) {
            uint32_t af[2][4];
            ldsm4(af[0], SA + swz(arow * 128 + ks * 32 + achunk));
            ldsm4(af[1], SA + swz((arow + 16) * 128 + ks * 32 + achunk));
            uint32_t bf[4][4];
            #pragma unroll
            for (int p = 0; p < 4; p++)
                ldsm4(bf[p], SB + swz((brow + p * 16) * 128 + ks * 32 + bchunk));
            #pragma unroll
            for (int mi = 0; mi < 2; mi++)
                #pragma unroll
                for (int j = 0; j < 8; j++)
                    mma_tf32(acc[mi][j], af[mi], &bf[j >> 1][(j & 1) * 2]);
        }
        if (++s == 3) s = 0;
    }

    #pragma unroll
    for (int mi = 0; mi < 2; mi++) {
        int r0 = m0 + warp_m + mi * 16 + (lane >> 2);
        #pragma unroll
        for (int j = 0; j < 8; j++) {
            int col = n0 + warp_n + j * 8 + (lane & 3) * 2;
            float bx = __ldg(bias + col), by = __ldg(bias + col + 1);
            if (OUT_MODE == 0) {
                float2 v0 = make_float2(acc[mi][j][0] + bx, acc[mi][j][1] + by);
                float2 v1 = make_float2(acc[mi][j][2] + bx, acc[mi][j][3] + by);
                *(float2*)&Cout[(size_t)r0 * NC + col] = v0;
                *(float2*)&Cout[(size_t)(r0 + 8) * NC + col] = v1;
            } else {
                // RNA-round to tf32 so the attention mma sees exact tf32 values
                float2 v0 = make_float2(rna_tf32(acc[mi][j][0] + bx), rna_tf32(acc[mi][j][1] + by));
                float2 v1 = make_float2(rna_tf32(acc[mi][j][2] + bx), rna_tf32(acc[mi][j][3] + by));
                int h = col >> 6, d = col & 63;
                int b0i = r0 >> 11, t0 = r0 & (NT - 1);
                int b1i = (r0 + 8) >> 11, t1 = (r0 + 8) & (NT - 1);
                *(float2*)&Cout[(((size_t)(b0i * NH + h) * NT) + t0) * ND + d] = v0;
                *(float2*)&Cout[(((size_t)(b1i * NH + h) * NT) + t1) * ND + d] = v1;
            }
        }
    }
}

// ---------------------------------------------------------------------------
// Tensor-core causal flash attention (tf32 mma.sync).
// Q block 128 rows, K/V tiles 64 keys. 256 threads = 8 warps, 16 q-rows each.
// Q fragments persistent in registers. P round-trips through warp-private smem.
// smem: Ks 16KB | Vt 16KB | P 32KB (P doubles as Q staging)  = 64KB
// ---------------------------------------------------------------------------
#define TQ 128
#define TK 64
#define KS_OFF 0
#define VT_OFF 16384
#define P_OFF  32768
#define ATTN_SMEM 65536

__global__ __launch_bounds__(256)
void attn_tc_kernel(const float* __restrict__ Q, const float* __restrict__ K,
                    const float* __restrict__ V, float* __restrict__ Y)
{
    extern __shared__ __align__(1024) char smem[];
    const uint32_t sb = smem_u32(smem);
    const int tid = threadIdx.x;
    const int wid = tid >> 5, lane = tid & 31;
    const int qb = blockIdx.x;
    const int bh = blockIdx.y;

    const float* Qg = Q + ((size_t)bh * NT + qb * TQ) * ND;
    const float* Kg = K + (size_t)bh * NT * ND;
    const float* Vg = V + (size_t)bh * NT * ND;

    // ---- stage Q tile into P region (two 128B-row halves by d) ----
    #pragma unroll
    for (int it = 0; it < 8; it++) {
        int idx = tid + it * 256;          // 0..2047 = 128 rows x 16 c4
        int row = idx >> 4, c4 = idx & 15;
        uint32_t addr = sb + P_OFF + (c4 >> 3) * 16384 + swz((uint32_t)(row * 128 + (c4 & 7) * 16));
        float4 v = *(const float4*)&Qg[(size_t)row * ND + c4 * 4];
        asm volatile("st.shared.v4.f32 [%0], {%1,%2,%3,%4};"
                     :: "r"(addr), "f"(v.x), "f"(v.y), "f"(v.z), "f"(v.w));
    }
    __syncthreads();

    const uint32_t arow = wid * 16 + (lane & 15);
    const uint32_t achunk = (lane & 16) ? 16u : 0u;
    const uint32_t brow8 = (lane & 7) + ((lane & 16) ? 8u : 0u);
    const uint32_t bchunk = (lane & 8) ? 16u : 0u;

    uint32_t aq[8][4];
    #pragma unroll
    for (int ks = 0; ks < 8; ks++)
        ldsm4(aq[ks], sb + P_OFF + (ks >> 2) * 16384 + swz(arow * 128 + (ks & 3) * 32 + achunk));

    float oacc[8][4];
    #pragma unroll
    for (int j = 0; j < 8; j++)
        #pragma unroll
        for (int q = 0; q < 4; q++) oacc[j][q] = 0.f;
    float m_[2] = {-1e30f, -1e30f}, l_[2] = {0.f, 0.f};

    const int kb_end = 2 * qb + 2;
    const int q0 = qb * TQ + wid * 16 + (lane >> 2);
    const int prow = wid * 16 + (lane >> 2);

    for (int kb = 0; kb < kb_end; kb++) {
        __syncthreads();    // all warps done with previous Ks/Vt

        // K tile via cp.async (coalesced, swizzled)
        #pragma unroll
        for (int it = 0; it < 4; it++) {
            int idx = tid + it * 256;      // 0..1023 = 64 rows x 16 c4
            int row = idx >> 4, c4 = idx & 15;
            uint32_t addr = sb + KS_OFF + (c4 >> 3) * 8192 + swz((uint32_t)(row * 128 + (c4 & 7) * 16));
            cp_async16(addr, &Kg[(size_t)(kb * TK + row) * ND + c4 * 4]);
        }
        cp_commit();

        // V tile transposed: thread handles (key = idx&63, c4 = idx>>6)
        // -> smem stores are 32 consecutive keys per warp = conflict-free
        #pragma unroll
        for (int it = 0; it < 4; it++) {
            int idx = tid + it * 256;
            int key = idx & 63, c4 = idx >> 6;
            float4 v = *(const float4*)&Vg[(size_t)(kb * TK + key) * ND + c4 * 4];
            uint32_t half = (uint32_t)(key >> 5) * 8192;
            uint32_t kbyt = (uint32_t)(key & 31) * 4;
            float vv[4] = {v.x, v.y, v.z, v.w};
            #pragma unroll
            for (int i2 = 0; i2 < 4; i2++) {
                uint32_t addr = sb + VT_OFF + half + swz((uint32_t)((c4 * 4 + i2) * 128) + kbyt);
                asm volatile("st.shared.f32 [%0], %1;" :: "r"(addr), "f"(vv[i2]));
            }
        }
        cp_wait0();
        __syncthreads();

        // ---- S = Q K^T ----
        float sacc[8][4];
        #pragma unroll
        for (int j = 0; j < 8; j++)
            #pragma unroll
            for (int q = 0; q < 4; q++) sacc[j][q] = 0.f;

        #pragma unroll
        for (int ks = 0; ks < 8; ks++) {
            uint32_t bkf[4][4];
            #pragma unroll
            for (int p = 0; p < 4; p++)
                ldsm4(bkf[p], sb + KS_OFF + (ks >> 2) * 8192 +
                              swz((p * 16 + brow8) * 128 + (ks & 3) * 32 + bchunk));
            #pragma unroll
            for (int j = 0; j < 8; j++)
                mma_tf32(sacc[j], aq[ks], &bkf[j >> 1][(j & 1) * 2]);
        }

        // ---- mask + online softmax + P store (warp-private) ----
        const float scale = 0.125f;
        const bool domask = (kb >= 2 * qb);
        const int kcbase = kb * TK + (lane & 3) * 2;
        #pragma unroll
        for (int h = 0; h < 2; h++) {
            const int qrow = q0 + 8 * h;
            float mx = -1e30f;
            #pragma unroll
            for (int j = 0; j < 8; j++) {
                #pragma unroll
                for (int c = 0; c < 2; c++) {
                    float v = sacc[j][2 * h + c] * scale;
                    if (domask && (kcbase + j * 8 + c) > qrow) v = -1e30f;
                    sacc[j][2 * h + c] = v;
                    mx = fmaxf(mx, v);
                }
            }
            mx = fmaxf(mx, __shfl_xor_sync(0xffffffffu, mx, 1));
            mx = fmaxf(mx, __shfl_xor_sync(0xffffffffu, mx, 2));
            float mnew = fmaxf(m_[h], mx);
            float f = __expf(m_[h] - mnew);
            float sum = 0.f;
            #pragma unroll
            for (int j = 0; j < 8; j++) {
                float p0 = __expf(sacc[j][2 * h] - mnew);
                float p1 = __expf(sacc[j][2 * h + 1] - mnew);
                sum += p0 + p1;
                p0 = rna_tf32(p0); p1 = rna_tf32(p1);
                uint32_t addr = sb + P_OFF + (j >> 2) * 16384 +
                    swz((uint32_t)((prow + 8 * h) * 128) + (j & 3) * 32 + (lane & 3) * 8);
                asm volatile("st.shared.v2.f32 [%0], {%1,%2};" :: "r"(addr), "f"(p0), "f"(p1));
            }
            sum += __shfl_xor_sync(0xffffffffu, sum, 1);
            sum += __shfl_xor_sync(0xffffffffu, sum, 2);
            l_[h] = l_[h] * f + sum;
            m_[h] = mnew;
            #pragma unroll
            for (int j = 0; j < 8; j++) {
                oacc[j][2 * h] *= f;
                oacc[j][2 * h + 1] *= f;
            }
        }
        __syncwarp();   // P rows are warp-private: intra-warp visibility only

        // ---- O += P V ----
        #pragma unroll
        for (int ks = 0; ks < 8; ks++) {
            uint32_t ap[4];
            ldsm4(ap, sb + P_OFF + (ks >> 2) * 16384 + swz(arow * 128 + (ks & 3) * 32 + achunk));
            uint32_t bvf[4][4];
            #pragma unroll
            for (int p = 0; p < 4; p++)
                ldsm4(bvf[p], sb + VT_OFF + (ks >> 2) * 8192 +
                              swz((p * 16 + brow8) * 128 + (ks & 3) * 32 + bchunk));
            #pragma unroll
            for (int j = 0; j < 8; j++)
                mma_tf32(oacc[j], ap, &bvf[j >> 1][(j & 1) * 2]);
        }
    }

    // ---- write Y[b, t, h*64 + d] ----
    const int b = bh >> 4, hh = bh & 15;
    #pragma unroll
    for (int h = 0; h < 2; h++) {
        int trow = qb * TQ + prow + 8 * h;
        float inv = 1.f / l_[h];
        float* Yg = Y + ((size_t)b * NT + trow) * NC + hh * ND;
        #pragma unroll
        for (int j = 0; j < 8; j++) {
            int col = j * 8 + (lane & 3) * 2;
            float2 v = make_float2(oacc[j][2 * h] * inv, oacc[j][2 * h + 1] * inv);
            *(float2*)&Yg[col] = v;
        }
    }
}

extern "C" void kernel_launch(void* const* d_in, const int* in_sizes, int n_in,
                              void* d_out, int out_size)
{
    const float* x  = (const float*)d_in[0];
    const float* Wq = (const float*)d_in[2];
    const float* bq = (const float*)d_in[3];
    const float* Wk = (const float*)d_in[4];
    const float* bk = (const float*)d_in[5];
    const float* Wv = (const float*)d_in[6];
    const float* bv = (const float*)d_in[7];
    const float* Wo = (const float*)d_in[8];
    const float* bo = (const float*)d_in[9];

    float *qp, *kp, *vp, *yp, *xr, *wr;
    cudaGetSymbolAddress((void**)&qp, g_Q);
    cudaGetSymbolAddress((void**)&kp, g_K);
    cudaGetSymbolAddress((void**)&vp, g_V);
    cudaGetSymbolAddress((void**)&yp, g_Y);
    cudaGetSymbolAddress((void**)&xr, g_xr);
    cudaGetSymbolAddress((void**)&wr, g_Wr);

    cudaFuncSetAttribute(gemm_tf32<0>,
                         cudaFuncAttributeMaxDynamicSharedMemorySize, GEMM_SMEM);
    cudaFuncSetAttribute(gemm_tf32<1>,
                         cudaFuncAttributeMaxDynamicSharedMemorySize, GEMM_SMEM);
    cudaFuncSetAttribute(attn_tc_kernel,
                         cudaFuncAttributeMaxDynamicSharedMemorySize, ATTN_SMEM);

    // tf32 RNA rounding pre-passes
    round_tf32_kernel<<<512, 256>>>(x,  xr,            NM * NC / 4);
    round_tf32_kernel<<<256, 256>>>(Wq, wr + 0*NC*NC,  NC * NC / 4);
    round_tf32_kernel<<<256, 256>>>(Wk, wr + 1*NC*NC,  NC * NC / 4);
    round_tf32_kernel<<<256, 256>>>(Wv, wr + 2*NC*NC,  NC * NC / 4);
    round_tf32_kernel<<<256, 256>>>(Wo, wr + 3*NC*NC,  NC * NC / 4);

    dim3 gridG(NC / 128, NM / 128);   // (8, 32) = 256 CTAs
    gemm_tf32<1><<<gridG, 256, GEMM_SMEM>>>(xr, wr + 0*NC*NC, bq, qp);
    gemm_tf32<1><<<gridG, 256, GEMM_SMEM>>>(xr, wr + 1*NC*NC, bk, kp);
    gemm_tf32<1><<<gridG, 256, GEMM_SMEM>>>(xr, wr + 2*NC*NC, bv, vp);

    attn_tc_kernel<<<dim3(NT / TQ, NB * NH), 256, ATTN_SMEM>>>(qp, kp, vp, yp);

    round_tf32_kernel<<<512, 256>>>(yp, yp, NM * NC / 4);   // round Y for final GEMM
    gemm_tf32<0><<<gridG, 256, GEMM_SMEM>>>(yp, wr + 3*NC*NC, bo, (float*)d_out);
}

// round 8
// speedup vs baseline: 3.9272x; 1.5615x over previous
#include <cuda_runtime.h>
#include <math.h>
#include <stdint.h>

#define NB 2
#define NT 2048
#define NC 1024
#define NH 16
#define ND 64
#define NM (NB*NT)            // 4096 rows
#define HSZ (NB*NH*NT*ND)     // elements per Q/K/V tensor

// Scratch (allocation-free)
__device__ float g_QKV[3*HSZ];
__device__ float g_Y[NM*NC];
__device__ float g_xr[NM*NC];       // tf32-rounded x
__device__ float g_Wr[4*NC*NC];     // tf32-rounded Wq,Wk,Wv,Wo

// ---------------------------------------------------------------------------
// PTX helpers (arch-agnostic: sm_80-era instructions only)
// ---------------------------------------------------------------------------
__device__ __forceinline__ uint32_t smem_u32(const void* p) {
    uint32_t a;
    asm("{ .reg .u64 t; cvta.to.shared.u64 t, %1; cvt.u32.u64 %0, t; }" : "=r"(a) : "l"(p));
    return a;
}
__device__ __forceinline__ void cp_async16(uint32_t dst, const void* src) {
    asm volatile("cp.async.cg.shared.global [%0], [%1], 16;\n" :: "r"(dst), "l"(src));
}
__device__ __forceinline__ void cp_commit() { asm volatile("cp.async.commit_group;\n" ::: "memory"); }
__device__ __forceinline__ void cp_wait1() { asm volatile("cp.async.wait_group 1;\n" ::: "memory"); }
__device__ __forceinline__ void cp_wait0() { asm volatile("cp.async.wait_group 0;\n" ::: "memory"); }

__device__ __forceinline__ void ldsm4(uint32_t* r, uint32_t addr) {
    asm volatile("ldmatrix.sync.aligned.m8n8.x4.shared.b16 {%0,%1,%2,%3}, [%4];"
        : "=r"(r[0]), "=r"(r[1]), "=r"(r[2]), "=r"(r[3]) : "r"(addr));
}
__device__ __forceinline__ void mma_tf32(float* d, const uint32_t* a, const uint32_t* b) {
    asm volatile(
        "mma.sync.aligned.m16n8k8.row.col.f32.tf32.tf32.f32 "
        "{%0,%1,%2,%3}, {%4,%5,%6,%7}, {%8,%9}, {%0,%1,%2,%3};"
        : "+f"(d[0]), "+f"(d[1]), "+f"(d[2]), "+f"(d[3])
        : "r"(a[0]), "r"(a[1]), "r"(a[2]), "r"(a[3]), "r"(b[0]), "r"(b[1]));
}
__device__ __forceinline__ uint32_t swz(uint32_t x) { return x ^ ((x >> 3) & 0x70); }
__device__ __forceinline__ float rna_tf32(float x) {
    uint32_t r;
    asm("cvt.rna.tf32.f32 %0, %1;" : "=r"(r) : "r"(__float_as_uint(x)));
    return __uint_as_float(r);
}

// ---------------------------------------------------------------------------
// RNA round-to-tf32 passes
// ---------------------------------------------------------------------------
__global__ void round_tf32_kernel(const float* __restrict__ in, float* __restrict__ out, int n4) {
    int i = blockIdx.x * blockDim.x + threadIdx.x;
    int stride = gridDim.x * blockDim.x;
    for (; i < n4; i += stride) {
        float4 v = ((const float4*)in)[i];
        float4 o;
        o.x = rna_tf32(v.x); o.y = rna_tf32(v.y);
        o.z = rna_tf32(v.z); o.w = rna_tf32(v.w);
        ((float4*)out)[i] = o;
    }
}

// All 4 weights in one launch: grid.y selects the weight
__global__ void round_w4_kernel(const float* __restrict__ w0, const float* __restrict__ w1,
                                const float* __restrict__ w2, const float* __restrict__ w3,
                                float* __restrict__ out) {
    const int g = blockIdx.y;
    const float* in = (g == 0) ? w0 : (g == 1) ? w1 : (g == 2) ? w2 : w3;
    float* o = out + (size_t)g * NC * NC;
    const int n4 = NC * NC / 4;
    int i = blockIdx.x * blockDim.x + threadIdx.x;
    int stride = gridDim.x * blockDim.x;
    for (; i < n4; i += stride) {
        float4 v = ((const float4*)in)[i];
        float4 r;
        r.x = rna_tf32(v.x); r.y = rna_tf32(v.y);
        r.z = rna_tf32(v.z); r.w = rna_tf32(v.w);
        ((float4*)o)[i] = r;
    }
}

// ---------------------------------------------------------------------------
// GEMM common: BM=128 BN=128 BK=32 floats, 3-stage cp.async (96KB smem).
// 256 threads = 8 warps in 4(m) x 2(n); warp tile 32x64; m16n8k8 tf32.
// ---------------------------------------------------------------------------
#define BKF 32
#define NCHUNK (NC / BKF)                  // 32
#define STAGE_A 16384                      // 128 rows * 128 B
#define STAGE_BYTES (2 * STAGE_A)          // 32 KB
#define GEMM_SMEM (3 * STAGE_BYTES)        // 96 KB

#define GEMM_PROLOGUE_BODY(WPTR) \
    extern __shared__ __align__(1024) char smem[]; \
    const uint32_t sbase = smem_u32(smem); \
    const int tid = threadIdx.x; \
    const int wid = tid >> 5, lane = tid & 31; \
    const int m0 = blockIdx.y * 128; \
    const int warp_m = (wid >> 1) * 32; \
    const int warp_n = (wid & 1) * 64; \
    const uint32_t arow = warp_m + (lane & 15); \
    const uint32_t achunk = (lane & 16) ? 16u : 0u; \
    const uint32_t brow = warp_n + (lane & 7) + ((lane & 16) ? 8u : 0u); \
    const uint32_t bchunk = (lane & 8) ? 16u : 0u; \
    float acc[2][8][4]; \
    _Pragma("unroll") \
    for (int mi = 0; mi < 2; mi++) \
        _Pragma("unroll") \
        for (int j = 0; j < 8; j++) \
            _Pragma("unroll") \
            for (int q = 0; q < 4; q++) acc[mi][j][q] = 0.f; \
    auto load_stage = [&](int s, int chunk) { \
        const int kc = chunk * BKF; \
        const uint32_t stA = sbase + s * STAGE_BYTES; \
        const uint32_t stB = stA + STAGE_A; \
        _Pragma("unroll") \
        for (int t = 0; t < 8; t++) { \
            int i = tid + t * 256; \
            uint32_t off; const float* src; \
            if (i < 1024) { \
                int r = i >> 3, c16 = i & 7; \
                off = stA + (uint32_t)(r * 128 + c16 * 16); \
                src = A + (size_t)(m0 + r) * NC + kc + c16 * 4; \
            } else { \
                int j = i - 1024; \
                int r = j >> 3, c16 = j & 7; \
                off = stB + (uint32_t)(r * 128 + c16 * 16); \
                src = (WPTR) + (size_t)(ncol0 + r) * NC + kc + c16 * 4; \
            } \
            cp_async16(swz(off), src); \
        } \
    }; \
    load_stage(0, 0); cp_commit(); \
    load_stage(1, 1); cp_commit(); \
    int s = 0; \
    for (int c = 0; c < NCHUNK; c++) { \
        cp_wait1(); \
        __syncthreads(); \
        if (c + 2 < NCHUNK) { \
            int sp = s + 2; if (sp >= 3) sp -= 3; \
            load_stage(sp, c + 2); \
        } \
        cp_commit(); \
        const uint32_t SA = sbase + s * STAGE_BYTES; \
        const uint32_t SB = SA + STAGE_A; \
        _Pragma("unroll") \
        for (int ks = 0; ks < 4; ks++) { \
            uint32_t af[2][4]; \
            ldsm4(af[0], SA + swz(arow * 128 + ks * 32 + achunk)); \
            ldsm4(af[1], SA + swz((arow + 16) * 128 + ks * 32 + achunk)); \
            uint32_t bf[4][4]; \
            _Pragma("unroll") \
            for (int p = 0; p < 4; p++) \
                ldsm4(bf[p], SB + swz((brow + p * 16) * 128 + ks * 32 + bchunk)); \
            _Pragma("unroll") \
            for (int mi = 0; mi < 2; mi++) \
                _Pragma("unroll") \
                for (int j = 0; j < 8; j++) \
                    mma_tf32(acc[mi][j], af[mi], &bf[j >> 1][(j & 1) * 2]); \
        } \
        if (++s == 3) s = 0; \
    }

// ---- Fused QKV GEMM: out cols 0..3071 over Wq|Wk|Wv, scatter to g_QKV ----
__global__ __launch_bounds__(256, 2)
void gemm_qkv(const float* __restrict__ A, const float* __restrict__ Wall,
              const float* __restrict__ bq, const float* __restrict__ bk,
              const float* __restrict__ bv, float* __restrict__ Out)
{
    const int proj = blockIdx.x >> 3;            // 0=Q 1=K 2=V
    const int ncol0 = (blockIdx.x & 7) * 128;    // column within projection
    const float* W = Wall + (size_t)proj * NC * NC;
    const float* bias = (proj == 0) ? bq : (proj == 1) ? bk : bv;
    float* Cout = Out + (size_t)proj * HSZ;

    GEMM_PROLOGUE_BODY(W)

    #pragma unroll
    for (int mi = 0; mi < 2; mi++) {
        int r0 = m0 + warp_m + mi * 16 + (lane >> 2);
        #pragma unroll
        for (int j = 0; j < 8; j++) {
            int col = ncol0 + warp_n + j * 8 + (lane & 3) * 2;
            float bx = __ldg(bias + col), by = __ldg(bias + col + 1);
            float2 v0 = make_float2(rna_tf32(acc[mi][j][0] + bx), rna_tf32(acc[mi][j][1] + by));
            float2 v1 = make_float2(rna_tf32(acc[mi][j][2] + bx), rna_tf32(acc[mi][j][3] + by));
            int h = col >> 6, d = col & 63;
            int b0i = r0 >> 11, t0 = r0 & (NT - 1);
            int b1i = (r0 + 8) >> 11, t1 = (r0 + 8) & (NT - 1);
            *(float2*)&Cout[(((size_t)(b0i * NH + h) * NT) + t0) * ND + d] = v0;
            *(float2*)&Cout[(((size_t)(b1i * NH + h) * NT) + t1) * ND + d] = v1;
        }
    }
}

// ---- Output projection GEMM: [M][N] row-major out ----
__global__ __launch_bounds__(256, 2)
void gemm_out(const float* __restrict__ A, const float* __restrict__ W,
              const float* __restrict__ bias, float* __restrict__ Cout)
{
    const int ncol0 = blockIdx.x * 128;

    GEMM_PROLOGUE_BODY(W)

    #pragma unroll
    for (int mi = 0; mi < 2; mi++) {
        int r0 = m0 + warp_m + mi * 16 + (lane >> 2);
        #pragma unroll
        for (int j = 0; j < 8; j++) {
            int col = ncol0 + warp_n + j * 8 + (lane & 3) * 2;
            float bx = __ldg(bias + col), by = __ldg(bias + col + 1);
            float2 v0 = make_float2(acc[mi][j][0] + bx, acc[mi][j][1] + by);
            float2 v1 = make_float2(acc[mi][j][2] + bx, acc[mi][j][3] + by);
            *(float2*)&Cout[(size_t)r0 * NC + col] = v0;
            *(float2*)&Cout[(size_t)(r0 + 8) * NC + col] = v1;
        }
    }
}

// ---------------------------------------------------------------------------
// Tensor-core causal flash attention (tf32 mma.sync), double-buffered K/V.
// Q block 128 rows, K/V tiles 64 keys. 256 threads = 8 warps, 16 q-rows each.
// smem: Ks[2] 2x16KB | Vt[2] 2x16KB | P 32KB (doubles as Q staging) = 96KB
// Y is tf32-rounded in the epilogue (feeds the O-projection GEMM directly).
// ---------------------------------------------------------------------------
#define TQ 128
#define TK 64
#define KS_OFF 0
#define VT_OFF 32768
#define P_OFF  65536
#define ATTN_SMEM 98304

__global__ __launch_bounds__(256)
void attn_tc_kernel(const float* __restrict__ Q, const float* __restrict__ K,
                    const float* __restrict__ V, float* __restrict__ Y)
{
    extern __shared__ __align__(1024) char smem[];
    const uint32_t sb = smem_u32(smem);
    const int tid = threadIdx.x;
    const int wid = tid >> 5, lane = tid & 31;
    const int qb = blockIdx.x;
    const int bh = blockIdx.y;

    const float* Qg = Q + ((size_t)bh * NT + qb * TQ) * ND;
    const float* Kg = K + (size_t)bh * NT * ND;
    const float* Vg = V + (size_t)bh * NT * ND;

    const int vkey = tid & 63;           // this thread's V key column
    const int vc0 = tid >> 6;            // c4 base (0..3), step 4

    // helper: issue K tile cp.async into buffer b
    auto load_K = [&](int kb, int bsel) {
        const uint32_t kbase = sb + KS_OFF + (uint32_t)bsel * 16384;
        #pragma unroll
        for (int it = 0; it < 4; it++) {
            int idx = tid + it * 256;
            int row = idx >> 4, c4 = idx & 15;
            uint32_t addr = kbase + (c4 >> 3) * 8192 + swz((uint32_t)(row * 128 + (c4 & 7) * 16));
            cp_async16(addr, &Kg[(size_t)(kb * TK + row) * ND + c4 * 4]);
        }
        cp_commit();
    };
    auto load_V_regs = [&](int kb, float4* vr) {
        #pragma unroll
        for (int it = 0; it < 4; it++)
            vr[it] = *(const float4*)&Vg[(size_t)(kb * TK + vkey) * ND + (vc0 + it * 4) * 4];
    };
    auto store_V = [&](int bsel, const float4* vr) {
        const uint32_t vbase = sb + VT_OFF + (uint32_t)bsel * 16384 + (uint32_t)(vkey >> 5) * 8192;
        const uint32_t kbyt = (uint32_t)(vkey & 31) * 4;
        #pragma unroll
        for (int it = 0; it < 4; it++) {
            int c4 = vc0 + it * 4;
            float vv[4] = {vr[it].x, vr[it].y, vr[it].z, vr[it].w};
            #pragma unroll
            for (int i2 = 0; i2 < 4; i2++) {
                uint32_t addr = vbase + swz((uint32_t)((c4 * 4 + i2) * 128) + kbyt);
                asm volatile("st.shared.f32 [%0], %1;" :: "r"(addr), "f"(vv[i2]));
            }
        }
    };

    // ---- prologue: issue K(0), stage Q into P region, stage V(0) ----
    load_K(0, 0);
    #pragma unroll
    for (int it = 0; it < 8; it++) {
        int idx = tid + it * 256;
        int row = idx >> 4, c4 = idx & 15;
        uint32_t addr = sb + P_OFF + (c4 >> 3) * 16384 + swz((uint32_t)(row * 128 + (c4 & 7) * 16));
        float4 v = *(const float4*)&Qg[(size_t)row * ND + c4 * 4];
        asm volatile("st.shared.v4.f32 [%0], {%1,%2,%3,%4};"
                     :: "r"(addr), "f"(v.x), "f"(v.y), "f"(v.z), "f"(v.w));
    }
    {
        float4 vr[4];
        load_V_regs(0, vr);
        store_V(0, vr);
    }
    cp_wait0();
    __syncthreads();

    const uint32_t arow = wid * 16 + (lane & 15);
    const uint32_t achunk = (lane & 16) ? 16u : 0u;
    const uint32_t brow8 = (lane & 7) + ((lane & 16) ? 8u : 0u);
    const uint32_t bchunk = (lane & 8) ? 16u : 0u;

    uint32_t aq[8][4];
    #pragma unroll
    for (int ks = 0; ks < 8; ks++)
        ldsm4(aq[ks], sb + P_OFF + (ks >> 2) * 16384 + swz(arow * 128 + (ks & 3) * 32 + achunk));

    float oacc[8][4];
    #pragma unroll
    for (int j = 0; j < 8; j++)
        #pragma unroll
        for (int q = 0; q < 4; q++) oacc[j][q] = 0.f;
    float m_[2] = {-1e30f, -1e30f}, l_[2] = {0.f, 0.f};

    const int kb_end = 2 * qb + 2;
    const int q0 = qb * TQ + wid * 16 + (lane >> 2);
    const int prow = wid * 16 + (lane >> 2);

    for (int kb = 0; kb < kb_end; kb++) {
        const int buf = kb & 1;
        const bool pre = (kb + 1 < kb_end);
        float4 vr[4];
        if (pre) {
            load_K(kb + 1, buf ^ 1);
            load_V_regs(kb + 1, vr);
        }

        // ---- S = Q K^T from Ks[buf] ----
        float sacc[8][4];
        #pragma unroll
        for (int j = 0; j < 8; j++)
            #pragma unroll
            for (int q = 0; q < 4; q++) sacc[j][q] = 0.f;

        const uint32_t kbase = sb + KS_OFF + (uint32_t)buf * 16384;
        #pragma unroll
        for (int ks = 0; ks < 8; ks++) {
            uint32_t bkf[4][4];
            #pragma unroll
            for (int p = 0; p < 4; p++)
                ldsm4(bkf[p], kbase + (ks >> 2) * 8192 +
                              swz((p * 16 + brow8) * 128 + (ks & 3) * 32 + bchunk));
            #pragma unroll
            for (int j = 0; j < 8; j++)
                mma_tf32(sacc[j], aq[ks], &bkf[j >> 1][(j & 1) * 2]);
        }

        // ---- mask + online softmax + P store (warp-private) ----
        const float scale = 0.125f;
        const bool domask = (kb >= 2 * qb);
        const int kcbase = kb * TK + (lane & 3) * 2;
        #pragma unroll
        for (int h = 0; h < 2; h++) {
            const int qrow = q0 + 8 * h;
            float mx = -1e30f;
            #pragma unroll
            for (int j = 0; j < 8; j++) {
                #pragma unroll
                for (int c = 0; c < 2; c++) {
                    float v = sacc[j][2 * h + c] * scale;
                    if (domask && (kcbase + j * 8 + c) > qrow) v = -1e30f;
                    sacc[j][2 * h + c] = v;
                    mx = fmaxf(mx, v);
                }
            }
            mx = fmaxf(mx, __shfl_xor_sync(0xffffffffu, mx, 1));
            mx = fmaxf(mx, __shfl_xor_sync(0xffffffffu, mx, 2));
            float mnew = fmaxf(m_[h], mx);
            float f = __expf(m_[h] - mnew);
            float sum = 0.f;
            #pragma unroll
            for (int j = 0; j < 8; j++) {
                float p0 = __expf(sacc[j][2 * h] - mnew);
                float p1 = __expf(sacc[j][2 * h + 1] - mnew);
                sum += p0 + p1;
                p0 = rna_tf32(p0); p1 = rna_tf32(p1);
                uint32_t addr = sb + P_OFF + (j >> 2) * 16384 +
                    swz((uint32_t)((prow + 8 * h) * 128) + (j & 3) * 32 + (lane & 3) * 8);
                asm volatile("st.shared.v2.f32 [%0], {%1,%2};" :: "r"(addr), "f"(p0), "f"(p1));
            }
            sum += __shfl_xor_sync(0xffffffffu, sum, 1);
            sum += __shfl_xor_sync(0xffffffffu, sum, 2);
            l_[h] = l_[h] * f + sum;
            m_[h] = mnew;
            #pragma unroll
            for (int j = 0; j < 8; j++) {
                oacc[j][2 * h] *= f;
                oacc[j][2 * h + 1] *= f;
            }
        }
        __syncwarp();   // P rows are warp-private

        if (pre) store_V(buf ^ 1, vr);   // write next V while this V is read below

        // ---- O += P V from Vt[buf] ----
        const uint32_t vbase = sb + VT_OFF + (uint32_t)buf * 16384;
        #pragma unroll
        for (int ks = 0; ks < 8; ks++) {
            uint32_t ap[4];
            ldsm4(ap, sb + P_OFF + (ks >> 2) * 16384 + swz(arow * 128 + (ks & 3) * 32 + achunk));
            uint32_t bvf[4][4];
            #pragma unroll
            for (int p = 0; p < 4; p++)
                ldsm4(bvf[p], vbase + (ks >> 2) * 8192 +
                              swz((p * 16 + brow8) * 128 + (ks & 3) * 32 + bchunk));
            #pragma unroll
            for (int j = 0; j < 8; j++)
                mma_tf32(oacc[j], ap, &bvf[j >> 1][(j & 1) * 2]);
        }

        cp_wait0();
        __syncthreads();
    }

    // ---- write Y[b, t, h*64 + d], rounded to tf32 for the O-projection ----
    const int b = bh >> 4, hh = bh & 15;
    #pragma unroll
    for (int h = 0; h < 2; h++) {
        int trow = qb * TQ + prow + 8 * h;
        float inv = 1.f / l_[h];
        float* Yg = Y + ((size_t)b * NT + trow) * NC + hh * ND;
        #pragma unroll
        for (int j = 0; j < 8; j++) {
            int col = j * 8 + (lane & 3) * 2;
            float2 v = make_float2(rna_tf32(oacc[j][2 * h] * inv),
                                   rna_tf32(oacc[j][2 * h + 1] * inv));
            *(float2*)&Yg[col] = v;
        }
    }
}

extern "C" void kernel_launch(void* const* d_in, const int* in_sizes, int n_in,
                              void* d_out, int out_size)
{
    const float* x  = (const float*)d_in[0];
    const float* Wq = (const float*)d_in[2];
    const float* bq = (const float*)d_in[3];
    const float* Wk = (const float*)d_in[4];
    const float* bk = (const float*)d_in[5];
    const float* Wv = (const float*)d_in[6];
    const float* bv = (const float*)d_in[7];
    const float* Wo = (const float*)d_in[8];
    const float* bo = (const float*)d_in[9];

    float *qkv, *yp, *xr, *wr;
    cudaGetSymbolAddress((void**)&qkv, g_QKV);
    cudaGetSymbolAddress((void**)&yp, g_Y);
    cudaGetSymbolAddress((void**)&xr, g_xr);
    cudaGetSymbolAddress((void**)&wr, g_Wr);

    cudaFuncSetAttribute(gemm_qkv,
                         cudaFuncAttributeMaxDynamicSharedMemorySize, GEMM_SMEM);
    cudaFuncSetAttribute(gemm_out,
                         cudaFuncAttributeMaxDynamicSharedMemorySize, GEMM_SMEM);
    cudaFuncSetAttribute(attn_tc_kernel,
                         cudaFuncAttributeMaxDynamicSharedMemorySize, ATTN_SMEM);

    // tf32 RNA rounding pre-passes (2 launches)
    round_tf32_kernel<<<512, 256>>>(x, xr, NM * NC / 4);
    round_w4_kernel<<<dim3(128, 4), 256>>>(Wq, Wk, Wv, Wo, wr);

    // fused Q/K/V projection: 768 CTAs
    gemm_qkv<<<dim3(24, NM / 128), 256, GEMM_SMEM>>>(xr, wr, bq, bk, bv, qkv);

    attn_tc_kernel<<<dim3(NT / TQ, NB * NH), 256, ATTN_SMEM>>>(
        qkv, qkv + HSZ, qkv + 2 * HSZ, yp);

    gemm_out<<<dim3(8, NM / 128), 256, GEMM_SMEM>>>(yp, wr + 3 * (size_t)NC * NC, bo, (float*)d_out);
}

// round 10
// speedup vs baseline: 7.9765x; 2.0311x over previous
#include <cuda_runtime.h>
#include <cuda_fp16.h>
#include <math.h>
#include <stdint.h>

#define NB 2
#define NT 2048
#define NC 1024
#define NH 16
#define ND 64
#define NM (NB*NT)            // 4096 rows
#define HSZ (NB*NH*NT*ND)     // elements per Q/K/V tensor

// Scratch (allocation-free)
__device__ __half g_QKV[3*HSZ];
__device__ __half g_Yh[NM*NC];
__device__ __half g_xh[NM*NC];      // fp16 x
__device__ __half g_Wh[4*NC*NC];    // fp16 Wq,Wk,Wv,Wo

// ---------------------------------------------------------------------------
// PTX helpers
// ---------------------------------------------------------------------------
__device__ __forceinline__ uint32_t smem_u32(const void* p) {
    uint32_t a;
    asm("{ .reg .u64 t; cvta.to.shared.u64 t, %1; cvt.u32.u64 %0, t; }" : "=r"(a) : "l"(p));
    return a;
}
__device__ __forceinline__ void cp_async16(uint32_t dst, const void* src) {
    asm volatile("cp.async.cg.shared.global [%0], [%1], 16;\n" :: "r"(dst), "l"(src));
}
__device__ __forceinline__ void cp_commit() { asm volatile("cp.async.commit_group;\n" ::: "memory"); }
__device__ __forceinline__ void cp_wait1() { asm volatile("cp.async.wait_group 1;\n" ::: "memory"); }
__device__ __forceinline__ void cp_wait0() { asm volatile("cp.async.wait_group 0;\n" ::: "memory"); }

__device__ __forceinline__ void ldsm4(uint32_t* r, uint32_t addr) {
    asm volatile("ldmatrix.sync.aligned.m8n8.x4.shared.b16 {%0,%1,%2,%3}, [%4];"
        : "=r"(r[0]), "=r"(r[1]), "=r"(r[2]), "=r"(r[3]) : "r"(addr));
}
__device__ __forceinline__ void ldsm4t(uint32_t* r, uint32_t addr) {
    asm volatile("ldmatrix.sync.aligned.m8n8.x4.trans.shared.b16 {%0,%1,%2,%3}, [%4];"
        : "=r"(r[0]), "=r"(r[1]), "=r"(r[2]), "=r"(r[3]) : "r"(addr));
}
__device__ __forceinline__ void mma_f16(float* d, const uint32_t* a, const uint32_t* b) {
    asm volatile(
        "mma.sync.aligned.m16n8k16.row.col.f32.f16.f16.f32 "
        "{%0,%1,%2,%3}, {%4,%5,%6,%7}, {%8,%9}, {%0,%1,%2,%3};"
        : "+f"(d[0]), "+f"(d[1]), "+f"(d[2]), "+f"(d[3])
        : "r"(a[0]), "r"(a[1]), "r"(a[2]), "r"(a[3]), "r"(b[0]), "r"(b[1]));
}
__device__ __forceinline__ uint32_t swz(uint32_t x) { return x ^ ((x >> 3) & 0x70); }

// ---------------------------------------------------------------------------
// fp32 -> fp16 convert passes
// ---------------------------------------------------------------------------
__global__ void f2h_kernel(const float* __restrict__ in, __half* __restrict__ out, int n4) {
    int i = blockIdx.x * blockDim.x + threadIdx.x;
    int stride = gridDim.x * blockDim.x;
    for (; i < n4; i += stride) {
        float4 v = ((const float4*)in)[i];
        __half2 h0 = __floats2half2_rn(v.x, v.y);
        __half2 h1 = __floats2half2_rn(v.z, v.w);
        ((uint2*)out)[i] = make_uint2(*(uint32_t*)&h0, *(uint32_t*)&h1);
    }
}
__global__ void f2h_w4_kernel(const float* __restrict__ w0, const float* __restrict__ w1,
                              const float* __restrict__ w2, const float* __restrict__ w3,
                              __half* __restrict__ out) {
    const int g = blockIdx.y;
    const float* in = (g == 0) ? w0 : (g == 1) ? w1 : (g == 2) ? w2 : w3;
    __half* o = out + (size_t)g * NC * NC;
    const int n4 = NC * NC / 4;
    int i = blockIdx.x * blockDim.x + threadIdx.x;
    int stride = gridDim.x * blockDim.x;
    for (; i < n4; i += stride) {
        float4 v = ((const float4*)in)[i];
        __half2 h0 = __floats2half2_rn(v.x, v.y);
        __half2 h1 = __floats2half2_rn(v.z, v.w);
        ((uint2*)o)[i] = make_uint2(*(uint32_t*)&h0, *(uint32_t*)&h1);
    }
}

// ---------------------------------------------------------------------------
// fp16 GEMM common: BM=128 BN=128 BK=64 halves (128B rows), 3-stage cp.async.
// 256 threads = 8 warps 4(m) x 2(n); warp tile 32x64; m16n8k16 f16, fp32 acc.
// ---------------------------------------------------------------------------
#define NCHUNK_H 16                        // 1024/64
#define STAGE_AH 16384                     // 128 rows * 128 B
#define STAGE_BYTES_H (2 * STAGE_AH)       // 32 KB
#define GEMM_SMEM (3 * STAGE_BYTES_H)      // 96 KB

#define GEMM_BODY_H(WPTR) \
    extern __shared__ __align__(1024) char smem[]; \
    const uint32_t sbase = smem_u32(smem); \
    const int tid = threadIdx.x; \
    const int wid = tid >> 5, lane = tid & 31; \
    const int m0 = blockIdx.y * 128; \
    const int warp_m = (wid >> 1) * 32; \
    const int warp_n = (wid & 1) * 64; \
    const uint32_t arow = warp_m + (lane & 15); \
    const uint32_t achunk = (lane & 16) ? 16u : 0u; \
    const uint32_t brow8 = (lane & 7) + ((lane & 16) ? 8u : 0u); \
    const uint32_t bchunk = (lane & 8) ? 16u : 0u; \
    float acc[2][8][4]; \
    _Pragma("unroll") \
    for (int mi = 0; mi < 2; mi++) \
        _Pragma("unroll") \
        for (int j = 0; j < 8; j++) \
            _Pragma("unroll") \
            for (int q = 0; q < 4; q++) acc[mi][j][q] = 0.f; \
    auto load_stage = [&](int s, int chunk) { \
        const int kc = chunk * 64; \
        const uint32_t stA = sbase + s * STAGE_BYTES_H; \
        const uint32_t stB = stA + STAGE_AH; \
        _Pragma("unroll") \
        for (int t = 0; t < 8; t++) { \
            int i = tid + t * 256; \
            uint32_t off; const __half* src; \
            if (i < 1024) { \
                int r = i >> 3, c16 = i & 7; \
                off = stA + (uint32_t)(r * 128 + c16 * 16); \
                src = A + (size_t)(m0 + r) * NC + kc + c16 * 8; \
            } else { \
                int j = i - 1024; \
                int r = j >> 3, c16 = j & 7; \
                off = stB + (uint32_t)(r * 128 + c16 * 16); \
                src = (WPTR) + (size_t)(ncol0 + r) * NC + kc + c16 * 8; \
            } \
            cp_async16(swz(off), src); \
        } \
    }; \
    load_stage(0, 0); cp_commit(); \
    load_stage(1, 1); cp_commit(); \
    int s = 0; \
    for (int c = 0; c < NCHUNK_H; c++) { \
        cp_wait1(); \
        __syncthreads(); \
        if (c + 2 < NCHUNK_H) { \
            int sp = s + 2; if (sp >= 3) sp -= 3; \
            load_stage(sp, c + 2); \
        } \
        cp_commit(); \
        const uint32_t SA = sbase + s * STAGE_BYTES_H; \
        const uint32_t SB = SA + STAGE_AH; \
        _Pragma("unroll") \
        for (int ks = 0; ks < 4; ks++) { \
            uint32_t af[2][4]; \
            ldsm4(af[0], SA + swz(arow * 128 + ks * 32 + achunk)); \
            ldsm4(af[1], SA + swz((arow + 16) * 128 + ks * 32 + achunk)); \
            uint32_t bf[4][4]; \
            _Pragma("unroll") \
            for (int p = 0; p < 4; p++) \
                ldsm4(bf[p], SB + swz((warp_n + p * 16 + brow8) * 128 + ks * 32 + bchunk)); \
            _Pragma("unroll") \
            for (int mi = 0; mi < 2; mi++) \
                _Pragma("unroll") \
                for (int j = 0; j < 8; j++) \
                    mma_f16(acc[mi][j], af[mi], &bf[j >> 1][(j & 1) * 2]); \
        } \
        if (++s == 3) s = 0; \
    }

// ---- Fused QKV GEMM: fp16 out scattered to [B,H,T,D] ----
__global__ __launch_bounds__(256, 2)
void gemm_qkv(const __half* __restrict__ A, const __half* __restrict__ Wall,
              const float* __restrict__ bq, const float* __restrict__ bk,
              const float* __restrict__ bv, __half* __restrict__ Out)
{
    const int proj = blockIdx.x >> 3;
    const int ncol0 = (blockIdx.x & 7) * 128;
    const __half* W = Wall + (size_t)proj * NC * NC;
    const float* bias = (proj == 0) ? bq : (proj == 1) ? bk : bv;
    __half* Cout = Out + (size_t)proj * HSZ;

    GEMM_BODY_H(W)

    #pragma unroll
    for (int mi = 0; mi < 2; mi++) {
        int r0 = m0 + warp_m + mi * 16 + (lane >> 2);
        #pragma unroll
        for (int j = 0; j < 8; j++) {
            int col = ncol0 + warp_n + j * 8 + (lane & 3) * 2;
            float bx = __ldg(bias + col), by = __ldg(bias + col + 1);
            __half2 v0 = __floats2half2_rn(acc[mi][j][0] + bx, acc[mi][j][1] + by);
            __half2 v1 = __floats2half2_rn(acc[mi][j][2] + bx, acc[mi][j][3] + by);
            int h = col >> 6, d = col & 63;
            int b0i = r0 >> 11, t0 = r0 & (NT - 1);
            int b1i = (r0 + 8) >> 11, t1 = (r0 + 8) & (NT - 1);
            *(__half2*)&Cout[(((size_t)(b0i * NH + h) * NT) + t0) * ND + d] = v0;
            *(__half2*)&Cout[(((size_t)(b1i * NH + h) * NT) + t1) * ND + d] = v1;
        }
    }
}

// ---- Output projection GEMM: fp32 out [M][N] ----
__global__ __launch_bounds__(256, 2)
void gemm_out(const __half* __restrict__ A, const __half* __restrict__ W,
              const float* __restrict__ bias, float* __restrict__ Cout)
{
    const int ncol0 = blockIdx.x * 128;

    GEMM_BODY_H(W)

    #pragma unroll
    for (int mi = 0; mi < 2; mi++) {
        int r0 = m0 + warp_m + mi * 16 + (lane >> 2);
        #pragma unroll
        for (int j = 0; j < 8; j++) {
            int col = ncol0 + warp_n + j * 8 + (lane & 3) * 2;
            float bx = __ldg(bias + col), by = __ldg(bias + col + 1);
            float2 v0 = make_float2(acc[mi][j][0] + bx, acc[mi][j][1] + by);
            float2 v1 = make_float2(acc[mi][j][2] + bx, acc[mi][j][3] + by);
            *(float2*)&Cout[(size_t)r0 * NC + col] = v0;
            *(float2*)&Cout[(size_t)(r0 + 8) * NC + col] = v1;
        }
    }
}

// ---------------------------------------------------------------------------
// fp16 tensor-core causal flash attention, double-buffered K/V via cp.async.
// Q block 128 rows, K/V tiles 64 keys. 256 threads = 8 warps, 16 q-rows each.
// V kept row-major; PV B-operand via ldmatrix.trans (no manual transpose).
// smem: K[2] 2x8KB | V[2] 2x8KB | P/Q 16KB = 48KB -> 2 CTAs/SM.
// ---------------------------------------------------------------------------
#define TQ 128
#define TK 64
#define VS_OFF 16384
#define P_OFF  32768
#define ATTN_SMEM 49152

__global__ __launch_bounds__(256, 2)
void attn_tc_kernel(const __half* __restrict__ Q, const __half* __restrict__ K,
                    const __half* __restrict__ V, __half* __restrict__ Y)
{
    extern __shared__ __align__(1024) char smem[];
    const uint32_t sb = smem_u32(smem);
    const int tid = threadIdx.x;
    const int wid = tid >> 5, lane = tid & 31;
    const int qb = (int)(gridDim.x - 1) - (int)blockIdx.x;   // heavy blocks first
    const int bh = blockIdx.y;

    const __half* Qg = Q + ((size_t)bh * NT + qb * TQ) * ND;
    const __half* Kg = K + (size_t)bh * NT * ND;
    const __half* Vg = V + (size_t)bh * NT * ND;

    auto load_K = [&](int kb, int bsel) {
        const uint32_t kbase = sb + (uint32_t)bsel * 8192;
        #pragma unroll
        for (int it = 0; it < 2; it++) {
            int idx = tid + it * 256;          // 0..511 = 64 rows x 8 segs
            int row = idx >> 3, c16 = idx & 7;
            cp_async16(kbase + swz((uint32_t)(row * 128 + c16 * 16)),
                       Kg + (size_t)(kb * TK + row) * ND + c16 * 8);
        }
    };
    auto load_V = [&](int kb, int bsel) {
        const uint32_t vbase = sb + VS_OFF + (uint32_t)bsel * 8192;
        #pragma unroll
        for (int it = 0; it < 2; it++) {
            int idx = tid + it * 256;
            int row = idx >> 3, c16 = idx & 7;
            cp_async16(vbase + swz((uint32_t)(row * 128 + c16 * 16)),
                       Vg + (size_t)(kb * TK + row) * ND + c16 * 8);
        }
    };

    // prologue: K(0), V(0), Q stage
    load_K(0, 0);
    load_V(0, 0);
    #pragma unroll
    for (int it = 0; it < 4; it++) {
        int idx = tid + it * 256;              // 0..1023 = 128 rows x 8 segs
        int row = idx >> 3, c16 = idx & 7;
        cp_async16(sb + P_OFF + swz((uint32_t)(row * 128 + c16 * 16)),
                   Qg + (size_t)row * ND + c16 * 8);
    }
    cp_commit();
    cp_wait0();
    __syncthreads();

    const uint32_t arow = wid * 16 + (lane & 15);
    const uint32_t achunk = (lane & 16) ? 16u : 0u;
    const uint32_t brow8 = (lane & 7) + ((lane & 16) ? 8u : 0u);
    const uint32_t bchunk = (lane & 8) ? 16u : 0u;
    // trans-ldsm (V): row = k0 + (lane&15), bytecol = d0*2 + ((lane&16)?16:0)
    const uint32_t vrow = lane & 15;
    const uint32_t vbyte = (lane & 16) ? 16u : 0u;

    // Q fragments (warp-private rows; P overwrites same region later - safe)
    uint32_t aq[4][4];
    #pragma unroll
    for (int ks = 0; ks < 4; ks++)
        ldsm4(aq[ks], sb + P_OFF + swz(arow * 128 + ks * 32 + achunk));

    float oacc[8][4];
    #pragma unroll
    for (int j = 0; j < 8; j++)
        #pragma unroll
        for (int q = 0; q < 4; q++) oacc[j][q] = 0.f;
    float m_[2] = {-1e30f, -1e30f}, l_[2] = {0.f, 0.f};

    const int kb_end = 2 * qb + 2;
    const int q0 = qb * TQ + wid * 16 + (lane >> 2);
    const int prow = wid * 16 + (lane >> 2);

    for (int kb = 0; kb < kb_end; kb++) {
        const int buf = kb & 1;
        const bool pre = (kb + 1 < kb_end);
        if (pre) {
            load_K(kb + 1, buf ^ 1);
            load_V(kb + 1, buf ^ 1);
            cp_commit();
        }

        // ---- S = Q K^T ----
        float sacc[8][4];
        #pragma unroll
        for (int j = 0; j < 8; j++)
            #pragma unroll
            for (int q = 0; q < 4; q++) sacc[j][q] = 0.f;

        const uint32_t kbase = sb + (uint32_t)buf * 8192;
        #pragma unroll
        for (int ks = 0; ks < 4; ks++) {
            uint32_t bkf[4][4];
            #pragma unroll
            for (int p = 0; p < 4; p++)
                ldsm4(bkf[p], kbase + swz((p * 16 + brow8) * 128 + ks * 32 + bchunk));
            #pragma unroll
            for (int j = 0; j < 8; j++)
                mma_f16(sacc[j], aq[ks], &bkf[j >> 1][(j & 1) * 2]);
        }

        // ---- mask + online softmax + P store (fp16, warp-private rows) ----
        const float scale = 0.125f;
        const bool domask = (kb >= 2 * qb);
        const int kcbase = kb * TK + (lane & 3) * 2;
        #pragma unroll
        for (int h = 0; h < 2; h++) {
            const int qrow = q0 + 8 * h;
            float mx = -1e30f;
            #pragma unroll
            for (int j = 0; j < 8; j++) {
                #pragma unroll
                for (int c = 0; c < 2; c++) {
                    float v = sacc[j][2 * h + c] * scale;
                    if (domask && (kcbase + j * 8 + c) > qrow) v = -1e30f;
                    sacc[j][2 * h + c] = v;
                    mx = fmaxf(mx, v);
                }
            }
            mx = fmaxf(mx, __shfl_xor_sync(0xffffffffu, mx, 1));
            mx = fmaxf(mx, __shfl_xor_sync(0xffffffffu, mx, 2));
            float mnew = fmaxf(m_[h], mx);
            float f = __expf(m_[h] - mnew);
            float sum = 0.f;
            #pragma unroll
            for (int j = 0; j < 8; j++) {
                float p0 = __expf(sacc[j][2 * h] - mnew);
                float p1 = __expf(sacc[j][2 * h + 1] - mnew);
                sum += p0 + p1;
                __half2 ph = __floats2half2_rn(p0, p1);
                uint32_t addr = sb + P_OFF +
                    swz((uint32_t)((prow + 8 * h) * 128) + j * 16 + (lane & 3) * 4);
                asm volatile("st.shared.b32 [%0], %1;" :: "r"(addr), "r"(*(uint32_t*)&ph));
            }
            sum += __shfl_xor_sync(0xffffffffu, sum, 1);
            sum += __shfl_xor_sync(0xffffffffu, sum, 2);
            l_[h] = l_[h] * f + sum;
            m_[h] = mnew;
            #pragma unroll
            for (int j = 0; j < 8; j++) {
                oacc[j][2 * h] *= f;
                oacc[j][2 * h + 1] *= f;
            }
        }
        __syncwarp();

        // ---- O += P V  (V row-major, B via ldmatrix.trans) ----
        const uint32_t vbase = sb + VS_OFF + (uint32_t)buf * 8192;
        #pragma unroll
        for (int ks = 0; ks < 4; ks++) {
            uint32_t ap[4];
            ldsm4(ap, sb + P_OFF + swz(arow * 128 + ks * 32 + achunk));
            uint32_t bvf[4][4];
            #pragma unroll
            for (int p = 0; p < 4; p++)
                ldsm4t(bvf[p], vbase + swz((ks * 16 + vrow) * 128 + p * 32 + vbyte));
            #pragma unroll
            for (int j = 0; j < 8; j++)
                mma_f16(oacc[j], ap, &bvf[j >> 1][(j & 1) * 2]);
        }

        if (pre) { cp_wait0(); }
        __syncthreads();
    }

    // ---- write Y (fp16) [b, t, hh*64 + d] ----
    const int b = bh >> 4, hh = bh & 15;
    #pragma unroll
    for (int h = 0; h < 2; h++) {
        int trow = qb * TQ + prow + 8 * h;
        float inv = 1.f / l_[h];
        __half* Yg = Y + ((size_t)b * NT + trow) * NC + hh * ND;
        #pragma unroll
        for (int j = 0; j < 8; j++) {
            int col = j * 8 + (lane & 3) * 2;
            __half2 v = __floats2half2_rn(oacc[j][2 * h] * inv, oacc[j][2 * h + 1] * inv);
            *(__half2*)&Yg[col] = v;
        }
    }
}

extern "C" void kernel_launch(void* const* d_in, const int* in_sizes, int n_in,
                              void* d_out, int out_size)
{
    const float* x  = (const float*)d_in[0];
    const float* Wq = (const float*)d_in[2];
    const float* bq = (const float*)d_in[3];
    const float* Wk = (const float*)d_in[4];
    const float* bk = (const float*)d_in[5];
    const float* Wv = (const float*)d_in[6];
    const float* bv = (const float*)d_in[7];
    const float* Wo = (const float*)d_in[8];
    const float* bo = (const float*)d_in[9];

    __half *qkv, *yh, *xh, *wh;
    cudaGetSymbolAddress((void**)&qkv, g_QKV);
    cudaGetSymbolAddress((void**)&yh, g_Yh);
    cudaGetSymbolAddress((void**)&xh, g_xh);
    cudaGetSymbolAddress((void**)&wh, g_Wh);

    cudaFuncSetAttribute(gemm_qkv,
                         cudaFuncAttributeMaxDynamicSharedMemorySize, GEMM_SMEM);
    cudaFuncSetAttribute(gemm_out,
                         cudaFuncAttributeMaxDynamicSharedMemorySize, GEMM_SMEM);
    cudaFuncSetAttribute(attn_tc_kernel,
                         cudaFuncAttributeMaxDynamicSharedMemorySize, ATTN_SMEM);

    // fp16 convert passes
    f2h_kernel<<<512, 256>>>(x, xh, NM * NC / 4);
    f2h_w4_kernel<<<dim3(128, 4), 256>>>(Wq, Wk, Wv, Wo, wh);

    // fused Q/K/V projection
    gemm_qkv<<<dim3(24, NM / 128), 256, GEMM_SMEM>>>(xh, wh, bq, bk, bv, qkv);

    attn_tc_kernel<<<dim3(NT / TQ, NB * NH), 256, ATTN_SMEM>>>(
        qkv, qkv + HSZ, qkv + 2 * HSZ, yh);

    gemm_out<<<dim3(8, NM / 128), 256, GEMM_SMEM>>>(yh, wh + 3 * (size_t)NC * NC, bo, (float*)d_out);
}

// round 13
// speedup vs baseline: 8.6959x; 1.0902x over previous
#include <cuda_runtime.h>
#include <cuda_fp16.h>
#include <math.h>
#include <stdint.h>

#define NB 2
#define NT 2048
#define NC 1024
#define NH 16
#define ND 64
#define NM (NB*NT)            // 4096 rows
#define HSZ (NB*NH*NT*ND)     // elements per Q/K/V tensor

// Scratch (allocation-free)
__device__ __half g_QKV[3*HSZ];
__device__ __half g_Yh[NM*NC];
__device__ __half g_xh[NM*NC];      // fp16 x
__device__ __half g_Wh[4*NC*NC];    // fp16 Wq,Wk,Wv,Wo

// ---------------------------------------------------------------------------
// PTX helpers
// ---------------------------------------------------------------------------
__device__ __forceinline__ uint32_t smem_u32(const void* p) {
    uint32_t a;
    asm("{ .reg .u64 t; cvta.to.shared.u64 t, %1; cvt.u32.u64 %0, t; }" : "=r"(a) : "l"(p));
    return a;
}
__device__ __forceinline__ void cp_async16(uint32_t dst, const void* src) {
    asm volatile("cp.async.cg.shared.global [%0], [%1], 16;\n" :: "r"(dst), "l"(src));
}
__device__ __forceinline__ void cp_commit() { asm volatile("cp.async.commit_group;\n" ::: "memory"); }
__device__ __forceinline__ void cp_wait1() { asm volatile("cp.async.wait_group 1;\n" ::: "memory"); }
__device__ __forceinline__ void cp_wait0() { asm volatile("cp.async.wait_group 0;\n" ::: "memory"); }

__device__ __forceinline__ void ldsm4(uint32_t* r, uint32_t addr) {
    asm volatile("ldmatrix.sync.aligned.m8n8.x4.shared.b16 {%0,%1,%2,%3}, [%4];"
        : "=r"(r[0]), "=r"(r[1]), "=r"(r[2]), "=r"(r[3]) : "r"(addr));
}
__device__ __forceinline__ void ldsm4t(uint32_t* r, uint32_t addr) {
    asm volatile("ldmatrix.sync.aligned.m8n8.x4.trans.shared.b16 {%0,%1,%2,%3}, [%4];"
        : "=r"(r[0]), "=r"(r[1]), "=r"(r[2]), "=r"(r[3]) : "r"(addr));
}
__device__ __forceinline__ void mma_f16(float* d, const uint32_t* a, const uint32_t* b) {
    asm volatile(
        "mma.sync.aligned.m16n8k16.row.col.f32.f16.f16.f32 "
        "{%0,%1,%2,%3}, {%4,%5,%6,%7}, {%8,%9}, {%0,%1,%2,%3};"
        : "+f"(d[0]), "+f"(d[1]), "+f"(d[2]), "+f"(d[3])
        : "r"(a[0]), "r"(a[1]), "r"(a[2]), "r"(a[3]), "r"(b[0]), "r"(b[1]));
}
__device__ __forceinline__ uint32_t swz(uint32_t x) { return x ^ ((x >> 3) & 0x70); }
__device__ __forceinline__ uint32_t h2u(float a, float b) {
    __half2 h = __floats2half2_rn(a, b);
    return *(uint32_t*)&h;
}

// ---------------------------------------------------------------------------
// single fp32 -> fp16 convert pass for x + 4 weights
// ---------------------------------------------------------------------------
#define NX4 (NM*NC/4)   // 2^20
#define NW4 (NC*NC/4)   // 2^18
__global__ void f2h_all(const float* __restrict__ x,
                        const float* __restrict__ w0, const float* __restrict__ w1,
                        const float* __restrict__ w2, const float* __restrict__ w3,
                        __half* __restrict__ xh, __half* __restrict__ wh)
{
    const int total = NX4 + 4 * NW4;
    int i = blockIdx.x * blockDim.x + threadIdx.x;
    int stride = gridDim.x * blockDim.x;
    for (; i < total; i += stride) {
        const float4* src; uint2* dst;
        if (i < NX4) {
            src = (const float4*)x + i;
            dst = (uint2*)xh + i;
        } else {
            int j = i - NX4;
            int g = j >> 18, off = j & (NW4 - 1);
            const float* w = (g == 0) ? w0 : (g == 1) ? w1 : (g == 2) ? w2 : w3;
            src = (const float4*)w + off;
            dst = (uint2*)(wh + (size_t)g * NC * NC) + off;
        }
        float4 v = *src;
        *dst = make_uint2(h2u(v.x, v.y), h2u(v.z, v.w));
    }
}

// ---------------------------------------------------------------------------
// fp16 GEMM common: BM=128 BN=128 BK=64 halves (128B rows), 3-stage cp.async.
// 256 threads = 8 warps 4(m) x 2(n); warp tile 32x64; m16n8k16 f16, fp32 acc.
// ---------------------------------------------------------------------------
#define NCHUNK_H 16
#define STAGE_AH 16384
#define STAGE_BYTES_H (2 * STAGE_AH)
#define GEMM_SMEM (3 * STAGE_BYTES_H)      // 96 KB

#define GEMM_BODY_H(WPTR) \
    extern __shared__ __align__(1024) char smem[]; \
    const uint32_t sbase = smem_u32(smem); \
    const int tid = threadIdx.x; \
    const int wid = tid >> 5, lane = tid & 31; \
    const int m0 = blockIdx.y * 128; \
    const int warp_m = (wid >> 1) * 32; \
    const int warp_n = (wid & 1) * 64; \
    const uint32_t arow = warp_m + (lane & 15); \
    const uint32_t achunk = (lane & 16) ? 16u : 0u; \
    const uint32_t brow8 = (lane & 7) + ((lane & 16) ? 8u : 0u); \
    const uint32_t bchunk = (lane & 8) ? 16u : 0u; \
    float acc[2][8][4]; \
    _Pragma("unroll") \
    for (int mi = 0; mi < 2; mi++) \
        _Pragma("unroll") \
        for (int j = 0; j < 8; j++) \
            _Pragma("unroll") \
            for (int q = 0; q < 4; q++) acc[mi][j][q] = 0.f; \
    auto load_stage = [&](int s, int chunk) { \
        const int kc = chunk * 64; \
        const uint32_t stA = sbase + s * STAGE_BYTES_H; \
        const uint32_t stB = stA + STAGE_AH; \
        _Pragma("unroll") \
        for (int t = 0; t < 8; t++) { \
            int i = tid + t * 256; \
            uint32_t off; const __half* src; \
            if (i < 1024) { \
                int r = i >> 3, c16 = i & 7; \
                off = stA + (uint32_t)(r * 128 + c16 * 16); \
                src = A + (size_t)(m0 + r) * NC + kc + c16 * 8; \
            } else { \
                int j = i - 1024; \
                int r = j >> 3, c16 = j & 7; \
                off = stB + (uint32_t)(r * 128 + c16 * 16); \
                src = (WPTR) + (size_t)(ncol0 + r) * NC + kc + c16 * 8; \
            } \
            cp_async16(swz(off), src); \
        } \
    }; \
    load_stage(0, 0); cp_commit(); \
    load_stage(1, 1); cp_commit(); \
    int s = 0; \
    for (int c = 0; c < NCHUNK_H; c++) { \
        cp_wait1(); \
        __syncthreads(); \
        if (c + 2 < NCHUNK_H) { \
            int sp = s + 2; if (sp >= 3) sp -= 3; \
            load_stage(sp, c + 2); \
        } \
        cp_commit(); \
        const uint32_t SA = sbase + s * STAGE_BYTES_H; \
        const uint32_t SB = SA + STAGE_AH; \
        _Pragma("unroll") \
        for (int ks = 0; ks < 4; ks++) { \
            uint32_t af[2][4]; \
            ldsm4(af[0], SA + swz(arow * 128 + ks * 32 + achunk)); \
            ldsm4(af[1], SA + swz((arow + 16) * 128 + ks * 32 + achunk)); \
            uint32_t bf[4][4]; \
            _Pragma("unroll") \
            for (int p = 0; p < 4; p++) \
                ldsm4(bf[p], SB + swz((warp_n + p * 16 + brow8) * 128 + ks * 32 + bchunk)); \
            _Pragma("unroll") \
            for (int mi = 0; mi < 2; mi++) \
                _Pragma("unroll") \
                for (int j = 0; j < 8; j++) \
                    mma_f16(acc[mi][j], af[mi], &bf[j >> 1][(j & 1) * 2]); \
        } \
        if (++s == 3) s = 0; \
    }

// ---- Fused QKV GEMM: fp16 out scattered to [B,H,T,D]; Q pre-scaled ----
#define QSCALE 0.18033688011112042f   // 0.125 * log2(e)

__global__ __launch_bounds__(256, 2)
void gemm_qkv(const __half* __restrict__ A, const __half* __restrict__ Wall,
              const float* __restrict__ bq, const float* __restrict__ bk,
              const float* __restrict__ bv, __half* __restrict__ Out)
{
    const int proj = blockIdx.x >> 3;
    const int ncol0 = (blockIdx.x & 7) * 128;
    const __half* W = Wall + (size_t)proj * NC * NC;
    const float* bias = (proj == 0) ? bq : (proj == 1) ? bk : bv;
    const float osc = (proj == 0) ? QSCALE : 1.0f;
    __half* Cout = Out + (size_t)proj * HSZ;

    GEMM_BODY_H(W)

    #pragma unroll
    for (int mi = 0; mi < 2; mi++) {
        int r0 = m0 + warp_m + mi * 16 + (lane >> 2);
        #pragma unroll
        for (int j = 0; j < 8; j++) {
            int col = ncol0 + warp_n + j * 8 + (lane & 3) * 2;
            float bx = __ldg(bias + col), by = __ldg(bias + col + 1);
            __half2 v0 = __floats2half2_rn((acc[mi][j][0] + bx) * osc, (acc[mi][j][1] + by) * osc);
            __half2 v1 = __floats2half2_rn((acc[mi][j][2] + bx) * osc, (acc[mi][j][3] + by) * osc);
            int h = col >> 6, d = col & 63;
            int b0i = r0 >> 11, t0 = r0 & (NT - 1);
            int b1i = (r0 + 8) >> 11, t1 = (r0 + 8) & (NT - 1);
            *(__half2*)&Cout[(((size_t)(b0i * NH + h) * NT) + t0) * ND + d] = v0;
            *(__half2*)&Cout[(((size_t)(b1i * NH + h) * NT) + t1) * ND + d] = v1;
        }
    }
}

// ---- Output projection GEMM: fp32 out [M][N] ----
__global__ __launch_bounds__(256, 2)
void gemm_out(const __half* __restrict__ A, const __half* __restrict__ W,
              const float* __restrict__ bias, float* __restrict__ Cout)
{
    const int ncol0 = blockIdx.x * 128;

    GEMM_BODY_H(W)

    #pragma unroll
    for (int mi = 0; mi < 2; mi++) {
        int r0 = m0 + warp_m + mi * 16 + (lane >> 2);
        #pragma unroll
        for (int j = 0; j < 8; j++) {
            int col = ncol0 + warp_n + j * 8 + (lane & 3) * 2;
            float bx = __ldg(bias + col), by = __ldg(bias + col + 1);
            float2 v0 = make_float2(acc[mi][j][0] + bx, acc[mi][j][1] + by);
            float2 v1 = make_float2(acc[mi][j][2] + bx, acc[mi][j][3] + by);
            *(float2*)&Cout[(size_t)r0 * NC + col] = v0;
            *(float2*)&Cout[(size_t)(r0 + 8) * NC + col] = v1;
        }
    }
}

// ---------------------------------------------------------------------------
// fp16 tensor-core causal flash attention.
// - P kept entirely in registers (C-frag == A-frag layout for m16n8k16)
// - scores arrive pre-scaled by 0.125*log2e -> exp2f softmax
// - diagonal (masked) tiles peeled out of the main loop
// smem: K[2] 2x8KB | V[2] 2x8KB | Q stage 16KB = 48KB -> 2 CTAs/SM.
// ---------------------------------------------------------------------------
#define TQ 128
#define TK 64
#define VS_OFF 16384
#define Q_OFF  32768
#define ATTN_SMEM 49152

__global__ __launch_bounds__(256, 2)
void attn_tc_kernel(const __half* __restrict__ Q, const __half* __restrict__ K,
                    const __half* __restrict__ V, __half* __restrict__ Y)
{
    extern __shared__ __align__(1024) char smem[];
    const uint32_t sb = smem_u32(smem);
    const int tid = threadIdx.x;
    const int wid = tid >> 5, lane = tid & 31;
    const int qb = (int)(gridDim.x - 1) - (int)blockIdx.x;   // heavy blocks first
    const int bh = blockIdx.y;

    const __half* Qg = Q + ((size_t)bh * NT + qb * TQ) * ND;
    const __half* Kg = K + (size_t)bh * NT * ND;
    const __half* Vg = V + (size_t)bh * NT * ND;

    auto load_K = [&](int kb, int bsel) {
        const uint32_t kbase = sb + (uint32_t)bsel * 8192;
        #pragma unroll
        for (int it = 0; it < 2; it++) {
            int idx = tid + it * 256;
            int row = idx >> 3, c16 = idx & 7;
            cp_async16(kbase + swz((uint32_t)(row * 128 + c16 * 16)),
                       Kg + (size_t)(kb * TK + row) * ND + c16 * 8);
        }
    };
    auto load_V = [&](int kb, int bsel) {
        const uint32_t vbase = sb + VS_OFF + (uint32_t)bsel * 8192;
        #pragma unroll
        for (int it = 0; it < 2; it++) {
            int idx = tid + it * 256;
            int row = idx >> 3, c16 = idx & 7;
            cp_async16(vbase + swz((uint32_t)(row * 128 + c16 * 16)),
                       Vg + (size_t)(kb * TK + row) * ND + c16 * 8);
        }
    };

    // prologue: K(0), V(0), Q stage
    load_K(0, 0);
    load_V(0, 0);
    #pragma unroll
    for (int it = 0; it < 4; it++) {
        int idx = tid + it * 256;
        int row = idx >> 3, c16 = idx & 7;
        cp_async16(sb + Q_OFF + swz((uint32_t)(row * 128 + c16 * 16)),
                   Qg + (size_t)row * ND + c16 * 8);
    }
    cp_commit();
    cp_wait0();
    __syncthreads();

    const uint32_t arow = wid * 16 + (lane & 15);
    const uint32_t achunk = (lane & 16) ? 16u : 0u;
    const uint32_t brow8 = (lane & 7) + ((lane & 16) ? 8u : 0u);
    const uint32_t bchunk = (lane & 8) ? 16u : 0u;
    const uint32_t vrow = lane & 15;
    const uint32_t vbyte = (lane & 16) ? 16u : 0u;

    uint32_t aq[4][4];
    #pragma unroll
    for (int ks = 0; ks < 4; ks++)
        ldsm4(aq[ks], sb + Q_OFF + swz(arow * 128 + ks * 32 + achunk));

    float oacc[8][4];
    #pragma unroll
    for (int j = 0; j < 8; j++)
        #pragma unroll
        for (int q = 0; q < 4; q++) oacc[j][q] = 0.f;
    float m_[2] = {-1e30f, -1e30f}, l_[2] = {0.f, 0.f};

    const int kb_end = 2 * qb + 2;
    const int q0 = qb * TQ + wid * 16 + (lane >> 2);

// One K/V tile iteration. DOMASK is a compile-time literal per expansion.
#define ATTN_TILE(DOMASK)                                                       \
{                                                                               \
    const int buf = kb & 1;                                                     \
    const bool pre = (kb + 1 < kb_end);                                         \
    if (pre) { load_K(kb + 1, buf ^ 1); load_V(kb + 1, buf ^ 1); }              \
    cp_commit();                                                                \
    float sacc[8][4];                                                           \
    _Pragma("unroll")                                                           \
    for (int j = 0; j < 8; j++)                                                 \
        _Pragma("unroll")                                                       \
        for (int q = 0; q < 4; q++) sacc[j][q] = 0.f;                           \
    const uint32_t kbase = sb + (uint32_t)buf * 8192;                           \
    _Pragma("unroll")                                                           \
    for (int ks = 0; ks < 4; ks++) {                                            \
        uint32_t bkf[4][4];                                                     \
        _Pragma("unroll")                                                       \
        for (int p = 0; p < 4; p++)                                             \
            ldsm4(bkf[p], kbase + swz((p * 16 + brow8) * 128 + ks * 32 + bchunk)); \
        _Pragma("unroll")                                                       \
        for (int j = 0; j < 8; j++)                                             \
            mma_f16(sacc[j], aq[ks], &bkf[j >> 1][(j & 1) * 2]);                \
    }                                                                           \
    const int kcbase = kb * TK + (lane & 3) * 2;                                \
    _Pragma("unroll")                                                           \
    for (int h = 0; h < 2; h++) {                                               \
        const int qrow = q0 + 8 * h;                                            \
        float mx = -1e30f;                                                      \
        _Pragma("unroll")                                                       \
        for (int j = 0; j < 8; j++) {                                           \
            _Pragma("unroll")                                                   \
            for (int c = 0; c < 2; c++) {                                       \
                float v = sacc[j][2 * h + c];                                   \
                if (DOMASK && (kcbase + j * 8 + c) > qrow) v = -1e30f;          \
                sacc[j][2 * h + c] = v;                                         \
                mx = fmaxf(mx, v);                                              \
            }                                                                   \
        }                                                                       \
        mx = fmaxf(mx, __shfl_xor_sync(0xffffffffu, mx, 1));                    \
        mx = fmaxf(mx, __shfl_xor_sync(0xffffffffu, mx, 2));                    \
        float mnew = fmaxf(m_[h], mx);                                          \
        float f = exp2f(m_[h] - mnew);                                          \
        float sum = 0.f;                                                        \
        _Pragma("unroll")                                                       \
        for (int j = 0; j < 8; j++) {                                           \
            float p0 = exp2f(sacc[j][2 * h] - mnew);                            \
            float p1 = exp2f(sacc[j][2 * h + 1] - mnew);                        \
            sum += p0 + p1;                                                     \
            sacc[j][2 * h] = p0; sacc[j][2 * h + 1] = p1;                       \
        }                                                                       \
        sum += __shfl_xor_sync(0xffffffffu, sum, 1);                            \
        sum += __shfl_xor_sync(0xffffffffu, sum, 2);                            \
        l_[h] = l_[h] * f + sum;                                                \
        m_[h] = mnew;                                                           \
        _Pragma("unroll")                                                       \
        for (int j = 0; j < 8; j++) {                                           \
            oacc[j][2 * h] *= f;                                                \
            oacc[j][2 * h + 1] *= f;                                            \
        }                                                                       \
    }                                                                           \
    /* pack P: C-frag -> A-frag, pure register conversion */                    \
    uint32_t ap[4][4];                                                          \
    _Pragma("unroll")                                                           \
    for (int ks = 0; ks < 4; ks++) {                                            \
        ap[ks][0] = h2u(sacc[2 * ks][0],     sacc[2 * ks][1]);                  \
        ap[ks][1] = h2u(sacc[2 * ks][2],     sacc[2 * ks][3]);                  \
        ap[ks][2] = h2u(sacc[2 * ks + 1][0], sacc[2 * ks + 1][1]);              \
        ap[ks][3] = h2u(sacc[2 * ks + 1][2], sacc[2 * ks + 1][3]);              \
    }                                                                           \
    const uint32_t vbase = sb + VS_OFF + (uint32_t)buf * 8192;                  \
    _Pragma("unroll")                                                           \
    for (int ks = 0; ks < 4; ks++) {                                            \
        uint32_t bvf[4][4];                                                     \
        _Pragma("unroll")                                                       \
        for (int p = 0; p < 4; p++)                                             \
            ldsm4t(bvf[p], vbase + swz((ks * 16 + vrow) * 128 + p * 32 + vbyte)); \
        _Pragma("unroll")                                                       \
        for (int j = 0; j < 8; j++)                                             \
            mma_f16(oacc[j], ap[ks], &bvf[j >> 1][(j & 1) * 2]);                \
    }                                                                           \
    if (pre) cp_wait0();                                                        \
    __syncthreads();                                                            \
}

    int kb = 0;
    const int kb_full = kb_end - 2;          // tiles strictly below the diagonal
    for (; kb < kb_full; kb++) ATTN_TILE(false)
    for (; kb < kb_end; kb++) ATTN_TILE(true)

#undef ATTN_TILE

    // ---- write Y (fp16) [b, t, hh*64 + d] ----
    const int b = bh >> 4, hh = bh & 15;
    const int prow = wid * 16 + (lane >> 2);
    #pragma unroll
    for (int h = 0; h < 2; h++) {
        int trow = qb * TQ + prow + 8 * h;
        float inv = 1.f / l_[h];
        __half* Yg = Y + ((size_t)b * NT + trow) * NC + hh * ND;
        #pragma unroll
        for (int j = 0; j < 8; j++) {
            int col = j * 8 + (lane & 3) * 2;
            __half2 v = __floats2half2_rn(oacc[j][2 * h] * inv, oacc[j][2 * h + 1] * inv);
            *(__half2*)&Yg[col] = v;
        }
    }
}

extern "C" void kernel_launch(void* const* d_in, const int* in_sizes, int n_in,
                              void* d_out, int out_size)
{
    const float* x  = (const float*)d_in[0];
    const float* Wq = (const float*)d_in[2];
    const float* bq = (const float*)d_in[3];
    const float* Wk = (const float*)d_in[4];
    const float* bk = (const float*)d_in[5];
    const float* Wv = (const float*)d_in[6];
    const float* bv = (const float*)d_in[7];
    const float* Wo = (const float*)d_in[8];
    const float* bo = (const float*)d_in[9];

    __half *qkv, *yh, *xh, *wh;
    cudaGetSymbolAddress((void**)&qkv, g_QKV);
    cudaGetSymbolAddress((void**)&yh, g_Yh);
    cudaGetSymbolAddress((void**)&xh, g_xh);
    cudaGetSymbolAddress((void**)&wh, g_Wh);

    cudaFuncSetAttribute(gemm_qkv,
                         cudaFuncAttributeMaxDynamicSharedMemorySize, GEMM_SMEM);
    cudaFuncSetAttribute(gemm_out,
                         cudaFuncAttributeMaxDynamicSharedMemorySize, GEMM_SMEM);
    cudaFuncSetAttribute(attn_tc_kernel,
                         cudaFuncAttributeMaxDynamicSharedMemorySize, ATTN_SMEM);

    // single fp16 convert pass (x + all 4 weights)
    f2h_all<<<592, 256>>>(x, Wq, Wk, Wv, Wo, xh, wh);

    // fused Q/K/V projection (Q pre-scaled by 0.125*log2e)
    gemm_qkv<<<dim3(24, NM / 128), 256, GEMM_SMEM>>>(xh, wh, bq, bk, bv, qkv);

    attn_tc_kernel<<<dim3(NT / TQ, NB * NH), 256, ATTN_SMEM>>>(
        qkv, qkv + HSZ, qkv + 2 * HSZ, yh);

    gemm_out<<<dim3(8, NM / 128), 256, GEMM_SMEM>>>(yh, wh + 3 * (size_t)NC * NC, bo, (float*)d_out);
}

// round 14
// speedup vs baseline: 9.0112x; 1.0363x over previous
#include <cuda_runtime.h>
#include <cuda_fp16.h>
#include <math.h>
#include <stdint.h>

#define NB 2
#define NT 2048
#define NC 1024
#define NH 16
#define ND 64
#define NM (NB*NT)            // 4096 rows
#define HSZ (NB*NH*NT*ND)     // elements per Q/K/V tensor

// Scratch (allocation-free)
__device__ __half g_QKV[3*HSZ];
__device__ __half g_Yh[NM*NC];
__device__ __half g_xh[NM*NC];      // fp16 x
__device__ __half g_Wh[4*NC*NC];    // fp16 Wq,Wk,Wv,Wo

// ---------------------------------------------------------------------------
// PTX helpers
// ---------------------------------------------------------------------------
__device__ __forceinline__ uint32_t smem_u32(const void* p) {
    uint32_t a;
    asm("{ .reg .u64 t; cvta.to.shared.u64 t, %1; cvt.u32.u64 %0, t; }" : "=r"(a) : "l"(p));
    return a;
}
__device__ __forceinline__ void cp_async16(uint32_t dst, const void* src) {
    asm volatile("cp.async.cg.shared.global [%0], [%1], 16;\n" :: "r"(dst), "l"(src));
}
__device__ __forceinline__ void cp_commit() { asm volatile("cp.async.commit_group;\n" ::: "memory"); }
__device__ __forceinline__ void cp_wait1() { asm volatile("cp.async.wait_group 1;\n" ::: "memory"); }
__device__ __forceinline__ void cp_wait0() { asm volatile("cp.async.wait_group 0;\n" ::: "memory"); }

__device__ __forceinline__ void ldsm4(uint32_t* r, uint32_t addr) {
    asm volatile("ldmatrix.sync.aligned.m8n8.x4.shared.b16 {%0,%1,%2,%3}, [%4];"
        : "=r"(r[0]), "=r"(r[1]), "=r"(r[2]), "=r"(r[3]) : "r"(addr));
}
__device__ __forceinline__ void ldsm4t(uint32_t* r, uint32_t addr) {
    asm volatile("ldmatrix.sync.aligned.m8n8.x4.trans.shared.b16 {%0,%1,%2,%3}, [%4];"
        : "=r"(r[0]), "=r"(r[1]), "=r"(r[2]), "=r"(r[3]) : "r"(addr));
}
__device__ __forceinline__ void mma_f16(float* d, const uint32_t* a, const uint32_t* b) {
    asm volatile(
        "mma.sync.aligned.m16n8k16.row.col.f32.f16.f16.f32 "
        "{%0,%1,%2,%3}, {%4,%5,%6,%7}, {%8,%9}, {%0,%1,%2,%3};"
        : "+f"(d[0]), "+f"(d[1]), "+f"(d[2]), "+f"(d[3])
        : "r"(a[0]), "r"(a[1]), "r"(a[2]), "r"(a[3]), "r"(b[0]), "r"(b[1]));
}
__device__ __forceinline__ uint32_t swz(uint32_t x) { return x ^ ((x >> 3) & 0x70); }
__device__ __forceinline__ uint32_t h2u(float a, float b) {
    __half2 h = __floats2half2_rn(a, b);
    return *(uint32_t*)&h;
}
// packed exp2: {lo,hi} floats -> f16x2 -> ex2.approx.f16x2 (first cvt src = HIGH half)
__device__ __forceinline__ uint32_t ex2_h2(float lo, float hi) {
    uint32_t r;
    asm("{ .reg .b32 t; cvt.rn.f16x2.f32 t, %1, %2; ex2.approx.f16x2 %0, t; }"
        : "=r"(r) : "f"(hi), "f"(lo));
    return r;
}

// ---------------------------------------------------------------------------
// single fp32 -> fp16 convert pass for x + 4 weights
// ---------------------------------------------------------------------------
#define NX4 (NM*NC/4)   // 2^20
#define NW4 (NC*NC/4)   // 2^18
__global__ void f2h_all(const float* __restrict__ x,
                        const float* __restrict__ w0, const float* __restrict__ w1,
                        const float* __restrict__ w2, const float* __restrict__ w3,
                        __half* __restrict__ xh, __half* __restrict__ wh)
{
    const int total = NX4 + 4 * NW4;
    int i = blockIdx.x * blockDim.x + threadIdx.x;
    int stride = gridDim.x * blockDim.x;
    for (; i < total; i += stride) {
        const float4* src; uint2* dst;
        if (i < NX4) {
            src = (const float4*)x + i;
            dst = (uint2*)xh + i;
        } else {
            int j = i - NX4;
            int g = j >> 18, off = j & (NW4 - 1);
            const float* w = (g == 0) ? w0 : (g == 1) ? w1 : (g == 2) ? w2 : w3;
            src = (const float4*)w + off;
            dst = (uint2*)(wh + (size_t)g * NC * NC) + off;
        }
        float4 v = *src;
        *dst = make_uint2(h2u(v.x, v.y), h2u(v.z, v.w));
    }
}

// ---------------------------------------------------------------------------
// fp16 GEMM common: BM=128 BN=128 BK=64 halves (128B rows), 3-stage cp.async.
// 256 threads = 8 warps 4(m) x 2(n); warp tile 32x64; m16n8k16 f16, fp32 acc.
// ---------------------------------------------------------------------------
#define NCHUNK_H 16
#define STAGE_AH 16384
#define STAGE_BYTES_H (2 * STAGE_AH)
#define GEMM_SMEM (3 * STAGE_BYTES_H)      // 96 KB

#define GEMM_BODY_H(WPTR) \
    extern __shared__ __align__(1024) char smem[]; \
    const uint32_t sbase = smem_u32(smem); \
    const int tid = threadIdx.x; \
    const int wid = tid >> 5, lane = tid & 31; \
    const int m0 = blockIdx.y * 128; \
    const int warp_m = (wid >> 1) * 32; \
    const int warp_n = (wid & 1) * 64; \
    const uint32_t arow = warp_m + (lane & 15); \
    const uint32_t achunk = (lane & 16) ? 16u : 0u; \
    const uint32_t brow8 = (lane & 7) + ((lane & 16) ? 8u : 0u); \
    const uint32_t bchunk = (lane & 8) ? 16u : 0u; \
    float acc[2][8][4]; \
    _Pragma("unroll") \
    for (int mi = 0; mi < 2; mi++) \
        _Pragma("unroll") \
        for (int j = 0; j < 8; j++) \
            _Pragma("unroll") \
            for (int q = 0; q < 4; q++) acc[mi][j][q] = 0.f; \
    auto load_stage = [&](int s, int chunk) { \
        const int kc = chunk * 64; \
        const uint32_t stA = sbase + s * STAGE_BYTES_H; \
        const uint32_t stB = stA + STAGE_AH; \
        _Pragma("unroll") \
        for (int t = 0; t < 8; t++) { \
            int i = tid + t * 256; \
            uint32_t off; const __half* src; \
            if (i < 1024) { \
                int r = i >> 3, c16 = i & 7; \
                off = stA + (uint32_t)(r * 128 + c16 * 16); \
                src = A + (size_t)(m0 + r) * NC + kc + c16 * 8; \
            } else { \
                int j = i - 1024; \
                int r = j >> 3, c16 = j & 7; \
                off = stB + (uint32_t)(r * 128 + c16 * 16); \
                src = (WPTR) + (size_t)(ncol0 + r) * NC + kc + c16 * 8; \
            } \
            cp_async16(swz(off), src); \
        } \
    }; \
    load_stage(0, 0); cp_commit(); \
    load_stage(1, 1); cp_commit(); \
    int s = 0; \
    for (int c = 0; c < NCHUNK_H; c++) { \
        cp_wait1(); \
        __syncthreads(); \
        if (c + 2 < NCHUNK_H) { \
            int sp = s + 2; if (sp >= 3) sp -= 3; \
            load_stage(sp, c + 2); \
        } \
        cp_commit(); \
        const uint32_t SA = sbase + s * STAGE_BYTES_H; \
        const uint32_t SB = SA + STAGE_AH; \
        _Pragma("unroll") \
        for (int ks = 0; ks < 4; ks++) { \
            uint32_t af[2][4]; \
            ldsm4(af[0], SA + swz(arow * 128 + ks * 32 + achunk)); \
            ldsm4(af[1], SA + swz((arow + 16) * 128 + ks * 32 + achunk)); \
            uint32_t bf[4][4]; \
            _Pragma("unroll") \
            for (int p = 0; p < 4; p++) \
                ldsm4(bf[p], SB + swz((warp_n + p * 16 + brow8) * 128 + ks * 32 + bchunk)); \
            _Pragma("unroll") \
            for (int mi = 0; mi < 2; mi++) \
                _Pragma("unroll") \
                for (int j = 0; j < 8; j++) \
                    mma_f16(acc[mi][j], af[mi], &bf[j >> 1][(j & 1) * 2]); \
        } \
        if (++s == 3) s = 0; \
    }

// ---- Fused QKV GEMM: fp16 out scattered to [B,H,T,D]; Q pre-scaled ----
#define QSCALE 0.18033688011112042f   // 0.125 * log2(e)

__global__ __launch_bounds__(256, 2)
void gemm_qkv(const __half* __restrict__ A, const __half* __restrict__ Wall,
              const float* __restrict__ bq, const float* __restrict__ bk,
              const float* __restrict__ bv, __half* __restrict__ Out)
{
    const int proj = blockIdx.x >> 3;
    const int ncol0 = (blockIdx.x & 7) * 128;
    const __half* W = Wall + (size_t)proj * NC * NC;
    const float* bias = (proj == 0) ? bq : (proj == 1) ? bk : bv;
    const float osc = (proj == 0) ? QSCALE : 1.0f;
    __half* Cout = Out + (size_t)proj * HSZ;

    GEMM_BODY_H(W)

    #pragma unroll
    for (int mi = 0; mi < 2; mi++) {
        int r0 = m0 + warp_m + mi * 16 + (lane >> 2);
        #pragma unroll
        for (int j = 0; j < 8; j++) {
            int col = ncol0 + warp_n + j * 8 + (lane & 3) * 2;
            float bx = __ldg(bias + col), by = __ldg(bias + col + 1);
            __half2 v0 = __floats2half2_rn((acc[mi][j][0] + bx) * osc, (acc[mi][j][1] + by) * osc);
            __half2 v1 = __floats2half2_rn((acc[mi][j][2] + bx) * osc, (acc[mi][j][3] + by) * osc);
            int h = col >> 6, d = col & 63;
            int b0i = r0 >> 11, t0 = r0 & (NT - 1);
            int b1i = (r0 + 8) >> 11, t1 = (r0 + 8) & (NT - 1);
            *(__half2*)&Cout[(((size_t)(b0i * NH + h) * NT) + t0) * ND + d] = v0;
            *(__half2*)&Cout[(((size_t)(b1i * NH + h) * NT) + t1) * ND + d] = v1;
        }
    }
}

// ---- Output projection GEMM: fp32 out [M][N] ----
__global__ __launch_bounds__(256, 2)
void gemm_out(const __half* __restrict__ A, const __half* __restrict__ W,
              const float* __restrict__ bias, float* __restrict__ Cout)
{
    const int ncol0 = blockIdx.x * 128;

    GEMM_BODY_H(W)

    #pragma unroll
    for (int mi = 0; mi < 2; mi++) {
        int r0 = m0 + warp_m + mi * 16 + (lane >> 2);
        #pragma unroll
        for (int j = 0; j < 8; j++) {
            int col = ncol0 + warp_n + j * 8 + (lane & 3) * 2;
            float bx = __ldg(bias + col), by = __ldg(bias + col + 1);
            float2 v0 = make_float2(acc[mi][j][0] + bx, acc[mi][j][1] + by);
            float2 v1 = make_float2(acc[mi][j][2] + bx, acc[mi][j][3] + by);
            *(float2*)&Cout[(size_t)r0 * NC + col] = v0;
            *(float2*)&Cout[(size_t)(r0 + 8) * NC + col] = v1;
        }
    }
}

// ---------------------------------------------------------------------------
// fp16 tensor-core causal flash attention.
// - P in registers; packed exp2 via ex2.approx.f16x2 directly into A-fragments
// - row sums (l) accumulated by an extra ones-column mma (no shuffles/FADDs)
// - diagonal (masked) tiles peeled out of the main loop
// smem: K[2] 2x8KB | V[2] 2x8KB | Q stage 16KB = 48KB -> 2 CTAs/SM.
// ---------------------------------------------------------------------------
#define TQ 128
#define TK 64
#define VS_OFF 16384
#define Q_OFF  32768
#define ATTN_SMEM 49152

__global__ __launch_bounds__(256, 2)
void attn_tc_kernel(const __half* __restrict__ Q, const __half* __restrict__ K,
                    const __half* __restrict__ V, __half* __restrict__ Y)
{
    extern __shared__ __align__(1024) char smem[];
    const uint32_t sb = smem_u32(smem);
    const int tid = threadIdx.x;
    const int wid = tid >> 5, lane = tid & 31;
    const int qb = (int)(gridDim.x - 1) - (int)blockIdx.x;   // heavy blocks first
    const int bh = blockIdx.y;

    const __half* Qg = Q + ((size_t)bh * NT + qb * TQ) * ND;
    const __half* Kg = K + (size_t)bh * NT * ND;
    const __half* Vg = V + (size_t)bh * NT * ND;

    auto load_K = [&](int kb, int bsel) {
        const uint32_t kbase = sb + (uint32_t)bsel * 8192;
        #pragma unroll
        for (int it = 0; it < 2; it++) {
            int idx = tid + it * 256;
            int row = idx >> 3, c16 = idx & 7;
            cp_async16(kbase + swz((uint32_t)(row * 128 + c16 * 16)),
                       Kg + (size_t)(kb * TK + row) * ND + c16 * 8);
        }
    };
    auto load_V = [&](int kb, int bsel) {
        const uint32_t vbase = sb + VS_OFF + (uint32_t)bsel * 8192;
        #pragma unroll
        for (int it = 0; it < 2; it++) {
            int idx = tid + it * 256;
            int row = idx >> 3, c16 = idx & 7;
            cp_async16(vbase + swz((uint32_t)(row * 128 + c16 * 16)),
                       Vg + (size_t)(kb * TK + row) * ND + c16 * 8);
        }
    };

    // prologue: K(0), V(0), Q stage
    load_K(0, 0);
    load_V(0, 0);
    #pragma unroll
    for (int it = 0; it < 4; it++) {
        int idx = tid + it * 256;
        int row = idx >> 3, c16 = idx & 7;
        cp_async16(sb + Q_OFF + swz((uint32_t)(row * 128 + c16 * 16)),
                   Qg + (size_t)row * ND + c16 * 8);
    }
    cp_commit();
    cp_wait0();
    __syncthreads();

    const uint32_t arow = wid * 16 + (lane & 15);
    const uint32_t achunk = (lane & 16) ? 16u : 0u;
    const uint32_t brow8 = (lane & 7) + ((lane & 16) ? 8u : 0u);
    const uint32_t bchunk = (lane & 8) ? 16u : 0u;
    const uint32_t vrow = lane & 15;
    const uint32_t vbyte = (lane & 16) ? 16u : 0u;

    uint32_t aq[4][4];
    #pragma unroll
    for (int ks = 0; ks < 4; ks++)
        ldsm4(aq[ks], sb + Q_OFF + swz(arow * 128 + ks * 32 + achunk));

    float oacc[8][4];
    #pragma unroll
    for (int j = 0; j < 8; j++)
        #pragma unroll
        for (int q = 0; q < 4; q++) oacc[j][q] = 0.f;
    float lacc[4] = {0.f, 0.f, 0.f, 0.f};   // ones-mma row-sum accumulator
    float m_[2] = {-1e30f, -1e30f};

    const uint32_t ones2[2] = {0x3C003C00u, 0x3C003C00u};   // fp16x2 {1,1}

    const int kb_end = 2 * qb + 2;
    const int q0 = qb * TQ + wid * 16 + (lane >> 2);

// One K/V tile iteration. DOMASK is a compile-time literal per expansion.
#define ATTN_TILE(DOMASK)                                                       \
{                                                                               \
    const int buf = kb & 1;                                                     \
    const bool pre = (kb + 1 < kb_end);                                         \
    if (pre) { load_K(kb + 1, buf ^ 1); load_V(kb + 1, buf ^ 1); }              \
    cp_commit();                                                                \
    float sacc[8][4];                                                           \
    _Pragma("unroll")                                                           \
    for (int j = 0; j < 8; j++)                                                 \
        _Pragma("unroll")                                                       \
        for (int q = 0; q < 4; q++) sacc[j][q] = 0.f;                           \
    const uint32_t kbase = sb + (uint32_t)buf * 8192;                           \
    _Pragma("unroll")                                                           \
    for (int ks = 0; ks < 4; ks++) {                                            \
        uint32_t bkf[4][4];                                                     \
        _Pragma("unroll")                                                       \
        for (int p = 0; p < 4; p++)                                             \
            ldsm4(bkf[p], kbase + swz((p * 16 + brow8) * 128 + ks * 32 + bchunk)); \
        _Pragma("unroll")                                                       \
        for (int j = 0; j < 8; j++)                                             \
            mma_f16(sacc[j], aq[ks], &bkf[j >> 1][(j & 1) * 2]);                \
    }                                                                           \
    const int kcbase = kb * TK + (lane & 3) * 2;                                \
    uint32_t ap[4][4];                                                          \
    _Pragma("unroll")                                                           \
    for (int h = 0; h < 2; h++) {                                               \
        const int qrow = q0 + 8 * h;                                            \
        float mx = -1e30f;                                                      \
        _Pragma("unroll")                                                       \
        for (int j = 0; j < 8; j++) {                                           \
            _Pragma("unroll")                                                   \
            for (int c = 0; c < 2; c++) {                                       \
                float v = sacc[j][2 * h + c];                                   \
                if (DOMASK && (kcbase + j * 8 + c) > qrow) v = -1e30f;          \
                sacc[j][2 * h + c] = v;                                         \
                mx = fmaxf(mx, v);                                              \
            }                                                                   \
        }                                                                       \
        mx = fmaxf(mx, __shfl_xor_sync(0xffffffffu, mx, 1));                    \
        mx = fmaxf(mx, __shfl_xor_sync(0xffffffffu, mx, 2));                    \
        float mnew = fmaxf(m_[h], mx);                                          \
        float f = exp2f(m_[h] - mnew);                                          \
        m_[h] = mnew;                                                           \
        /* packed exp2 straight into the A-fragment halves */                   \
        _Pragma("unroll")                                                       \
        for (int j = 0; j < 8; j++)                                             \
            ap[j >> 1][(j & 1) * 2 + h] =                                       \
                ex2_h2(sacc[j][2 * h] - mnew, sacc[j][2 * h + 1] - mnew);       \
        lacc[2 * h]     *= f;                                                   \
        lacc[2 * h + 1] *= f;                                                   \
        _Pragma("unroll")                                                       \
        for (int j = 0; j < 8; j++) {                                           \
            oacc[j][2 * h] *= f;                                                \
            oacc[j][2 * h + 1] *= f;                                            \
        }                                                                       \
    }                                                                           \
    const uint32_t vbase = sb + VS_OFF + (uint32_t)buf * 8192;                  \
    _Pragma("unroll")                                                           \
    for (int ks = 0; ks < 4; ks++) {                                            \
        uint32_t bvf[4][4];                                                     \
        _Pragma("unroll")                                                       \
        for (int p = 0; p < 4; p++)                                             \
            ldsm4t(bvf[p], vbase + swz((ks * 16 + vrow) * 128 + p * 32 + vbyte)); \
        _Pragma("unroll")                                                       \
        for (int j = 0; j < 8; j++)                                             \
            mma_f16(oacc[j], ap[ks], &bvf[j >> 1][(j & 1) * 2]);                \
        mma_f16(lacc, ap[ks], ones2);   /* l += row-sum of P (ones column) */   \
    }                                                                           \
    if (pre) cp_wait0();                                                        \
    __syncthreads();                                                            \
}

    int kb = 0;
    const int kb_full = kb_end - 2;          // tiles strictly below the diagonal
    for (; kb < kb_full; kb++) ATTN_TILE(false)
    for (; kb < kb_end; kb++) ATTN_TILE(true)

#undef ATTN_TILE

    // ---- write Y (fp16) [b, t, hh*64 + d] ----
    const int b = bh >> 4, hh = bh & 15;
    const int prow = wid * 16 + (lane >> 2);
    #pragma unroll
    for (int h = 0; h < 2; h++) {
        int trow = qb * TQ + prow + 8 * h;
        float inv = 1.f / lacc[2 * h];
        __half* Yg = Y + ((size_t)b * NT + trow) * NC + hh * ND;
        #pragma unroll
        for (int j = 0; j < 8; j++) {
            int col = j * 8 + (lane & 3) * 2;
            __half2 v = __floats2half2_rn(oacc[j][2 * h] * inv, oacc[j][2 * h + 1] * inv);
            *(__half2*)&Yg[col] = v;
        }
    }
}

extern "C" void kernel_launch(void* const* d_in, const int* in_sizes, int n_in,
                              void* d_out, int out_size)
{
    const float* x  = (const float*)d_in[0];
    const float* Wq = (const float*)d_in[2];
    const float* bq = (const float*)d_in[3];
    const float* Wk = (const float*)d_in[4];
    const float* bk = (const float*)d_in[5];
    const float* Wv = (const float*)d_in[6];
    const float* bv = (const float*)d_in[7];
    const float* Wo = (const float*)d_in[8];
    const float* bo = (const float*)d_in[9];

    __half *qkv, *yh, *xh, *wh;
    cudaGetSymbolAddress((void**)&qkv, g_QKV);
    cudaGetSymbolAddress((void**)&yh, g_Yh);
    cudaGetSymbolAddress((void**)&xh, g_xh);
    cudaGetSymbolAddress((void**)&wh, g_Wh);

    cudaFuncSetAttribute(gemm_qkv,
                         cudaFuncAttributeMaxDynamicSharedMemorySize, GEMM_SMEM);
    cudaFuncSetAttribute(gemm_out,
                         cudaFuncAttributeMaxDynamicSharedMemorySize, GEMM_SMEM);
    cudaFuncSetAttribute(attn_tc_kernel,
                         cudaFuncAttributeMaxDynamicSharedMemorySize, ATTN_SMEM);

    // single fp16 convert pass (x + all 4 weights)
    f2h_all<<<592, 256>>>(x, Wq, Wk, Wv, Wo, xh, wh);

    // fused Q/K/V projection (Q pre-scaled by 0.125*log2e)
    gemm_qkv<<<dim3(24, NM / 128), 256, GEMM_SMEM>>>(xh, wh, bq, bk, bv, qkv);

    attn_tc_kernel<<<dim3(NT / TQ, NB * NH), 256, ATTN_SMEM>>>(
        qkv, qkv + HSZ, qkv + 2 * HSZ, yh);

    gemm_out<<<dim3(8, NM / 128), 256, GEMM_SMEM>>>(yh, wh + 3 * (size_t)NC * NC, bo, (float*)d_out);
}